// round 5
// baseline (speedup 1.0000x reference)
#include <cuda_runtime.h>
#include <cstdint>

#define H 128
#define MAXN 50000
#define BN_EPS 1e-5f

// ---------------- device scratch ---------------------------------------------
__device__ float g_h[MAXN * H];
__device__ float g_t[MAXN * H];
__device__ float g_agg[MAXN * H];
// W fragments: [slot(9)][J(16)][T(16)][lane(32)] = (hi0, hi1, lo0, lo1)
__device__ float4 g_Wfrag[9 * 16 * 16 * 32];
__device__ float g_bf[9 * H];

// ---------------- helpers -------------------------------------------------------
__device__ __forceinline__ float tf32_rna(float x) {
    uint32_t r;
    asm("cvt.rna.tf32.f32 %0, %1;" : "=r"(r) : "f"(x));
    return __uint_as_float(r);
}

// D += A(16x8 row-major tf32) * B(8x8 col-major tf32), fp32 accum
__device__ __forceinline__ void mma_tf32(float* d, const uint32_t* a,
                                         uint32_t b0, uint32_t b1) {
    asm volatile(
        "mma.sync.aligned.m16n8k8.row.col.f32.tf32.tf32.f32 "
        "{%0,%1,%2,%3}, {%4,%5,%6,%7}, {%8,%9}, {%0,%1,%2,%3};"
        : "+f"(d[0]), "+f"(d[1]), "+f"(d[2]), "+f"(d[3])
        : "r"(a[0]), "r"(a[1]), "r"(a[2]), "r"(a[3]), "r"(b0), "r"(b1));
}

// ---------------- small kernels -------------------------------------------------
__global__ void zero_out_kernel(float* out, int n) {
    int i = blockIdx.x * blockDim.x + threadIdx.x;
    if (i < n) out[i] = 0.0f;
}

// Fold BN into weights AND convert to tf32 hi/lo mma fragments.
// slot = 3*layer + {0: pre-BN-folded lin, 1: post-BN-folded mlp_w1, 2: mlp_w2}
__global__ void fold_all_kernel(
    const float* __restrict__ bn_g, const float* __restrict__ bn_b,
    const float* __restrict__ bn_m, const float* __restrict__ bn_v,
    const float* __restrict__ lin_w, const float* __restrict__ lin_b,
    const float* __restrict__ mbn_g, const float* __restrict__ mbn_b,
    const float* __restrict__ mbn_m, const float* __restrict__ mbn_v,
    const float* __restrict__ mlp_w1, const float* __restrict__ mlp_b1,
    const float* __restrict__ mlp_w2, const float* __restrict__ mlp_b2,
    float4* __restrict__ Wf, float* __restrict__ bo) {
    const int slot = blockIdx.x;       // 0..8
    const int l = slot / 3;
    const int type = slot % 3;
    const int n = threadIdx.x;         // output channel

    __shared__ float ss[H], st[H];
    float sv = 1.0f, tv = 0.0f;
    if (type == 0) {
        float s = bn_g[l * H + n] * rsqrtf(bn_v[l * H + n] + BN_EPS);
        ss[n] = s;
        st[n] = bn_b[l * H + n] - bn_m[l * H + n] * s;
        __syncthreads();
    } else if (type == 1) {
        sv = mbn_g[l * H + n] * rsqrtf(mbn_v[l * H + n] + BN_EPS);
        tv = mbn_b[l * H + n] - mbn_m[l * H + n] * sv;
    }

    const float* W;
    if (type == 0)      W = lin_w  + (size_t)l * H * H;
    else if (type == 1) W = mlp_w1 + (size_t)l * H * H;
    else                W = mlp_w2 + (size_t)l * H * H;

    float bias_acc;
    if (type == 0)      bias_acc = lin_b[l * H + n];
    else if (type == 1) bias_acc = mlp_b1[l * H + n] * sv + tv;
    else                bias_acc = mlp_b2[l * H + n];

    const int J = n >> 3;
    const int g = n & 7;
    for (int cc = 0; cc < H; cc++) {
        float w = W[cc * H + n];
        float v;
        if (type == 0) { v = ss[cc] * w; bias_acc += st[cc] * w; }
        else if (type == 1) v = w * sv;
        else v = w;
        float hi = tf32_rna(v);
        float lo = tf32_rna(v - hi);
        int T = cc >> 3;
        int ki = cc & 7;
        int lane = g * 4 + (ki & 3);
        float* dst = (float*)&Wf[(((size_t)slot * 16 + J) * 16 + T) * 32 + lane];
        int c2 = (ki >> 2) & 1;
        dst[c2]     = hi;
        dst[2 + c2] = lo;
    }
    bo[slot * H + n] = bias_acc;
}

// one warp per edge: agg[dst] += feat[src]
__global__ void scatter_kernel(const float* __restrict__ feat,
                               const int* __restrict__ ei,
                               float* __restrict__ agg, int Ee) {
    int gi = blockIdx.x * blockDim.x + threadIdx.x;
    int e = gi >> 5;
    int lane = threadIdx.x & 31;
    if (e >= Ee) return;
    int src = __ldg(ei + e);
    int dst = __ldg(ei + Ee + e);
    float4 v = *(const float4*)(feat + (size_t)src * H + lane * 4);
    float* p = agg + (size_t)dst * H + lane * 4;
    asm volatile("red.global.add.v4.f32 [%0], {%1, %2, %3, %4};"
                 :: "l"(p), "f"(v.x), "f"(v.y), "f"(v.z), "f"(v.w) : "memory");
}

// ---------------- mma.sync 3xtf32 GEMM: C[M,128] = op(A[M,128] @ W + b) --------
// CTA: 128 rows x 128 cols, 8 warps (4 row-blocks x 2 col-halves).
// Warp: 32 rows x 64 cols = 2 m-atoms x 8 n-atoms of m16n8k8; K in 4 chunks of 32.
#define APAD 34   // floats per staged row (conflict-free STS banks)
template <bool RELU, bool WAGG, bool RDOUT, bool GATH>
__global__ void __launch_bounds__(256)
gemm_mma(const float* __restrict__ A, const int* __restrict__ gather,
         const float4* __restrict__ Wf, const float* __restrict__ bias,
         float* __restrict__ C, float* __restrict__ Agg,
         const float* __restrict__ eps, int layer,
         const int* __restrict__ batch, const float* __restrict__ ro_w,
         const float* __restrict__ ro_b, float* __restrict__ gout, int M) {
    __shared__ float sAhi[128 * APAD];
    __shared__ float sAlo[128 * APAD];
    __shared__ float sBias[H];
    __shared__ float sRo[H];

    const int tid = threadIdx.x;
    const int wid = tid >> 5, lid = tid & 31;
    const int m0 = blockIdx.x * 128;
    const int J0 = (wid >> 2) * 8;       // n-atom base for this warp

    if (tid < H) {
        sBias[tid] = bias[tid];
        if (RDOUT) sRo[tid] = ro_w[tid];
    }

    float acc[2][8][4];
#pragma unroll
    for (int m = 0; m < 2; m++)
#pragma unroll
        for (int j = 0; j < 8; j++)
#pragma unroll
            for (int r = 0; r < 4; r++) acc[m][j][r] = 0.0f;

    for (int chunk = 0; chunk < 4; chunk++) {
        __syncthreads();
        // ---- stage A chunk [128 rows x 32 k] as hi/lo, column-interleaved ----
#pragma unroll
        for (int i = 0; i < 4; i++) {
            int idx = tid + i * 256;        // 0..1023 float4 tasks
            int row = idx >> 3;
            int sub = idx & 7;
            int katom = sub >> 1, hh = sub & 1;
            int kk0 = katom * 8 + hh * 4;
            int m = m0 + row;
            float4 v = make_float4(0.f, 0.f, 0.f, 0.f);
            if (m < M) {
                const float* src;
                if (GATH) src = A + (size_t)__ldg(gather + m) * H;
                else      src = A + (size_t)m * H;
                v = *(const float4*)(src + chunk * 32 + kk0);
            }
            float e[4] = {v.x, v.y, v.z, v.w};
            float* dh = &sAhi[row * APAD + katom * 8 + hh];
            float* dl = &sAlo[row * APAD + katom * 8 + hh];
#pragma unroll
            for (int j = 0; j < 4; j++) {
                float hi = tf32_rna(e[j]);
                dh[j * 2] = hi;
                dl[j * 2] = tf32_rna(e[j] - hi);
            }
        }
        __syncthreads();

        // ---- mma over the chunk's 4 k-atoms ----
#pragma unroll
        for (int t = 0; t < 4; t++) {
            const int T = chunk * 4 + t;
            uint32_t ahi[2][4], alo[2][4];
#pragma unroll
            for (int m = 0; m < 2; m++) {
                int row_s = (wid & 3) * 32 + m * 16 + (lid >> 2);
                int coff = t * 8 + (lid & 3) * 2;
                float2 h0 = *(const float2*)&sAhi[row_s * APAD + coff];
                float2 h1 = *(const float2*)&sAhi[(row_s + 8) * APAD + coff];
                float2 l0 = *(const float2*)&sAlo[row_s * APAD + coff];
                float2 l1 = *(const float2*)&sAlo[(row_s + 8) * APAD + coff];
                ahi[m][0] = __float_as_uint(h0.x); ahi[m][1] = __float_as_uint(h1.x);
                ahi[m][2] = __float_as_uint(h0.y); ahi[m][3] = __float_as_uint(h1.y);
                alo[m][0] = __float_as_uint(l0.x); alo[m][1] = __float_as_uint(l1.x);
                alo[m][2] = __float_as_uint(l0.y); alo[m][3] = __float_as_uint(l1.y);
            }
#pragma unroll
            for (int j = 0; j < 8; j++) {
                float4 wf = __ldg(&Wf[((size_t)(J0 + j) * 16 + T) * 32 + lid]);
                uint32_t bh0 = __float_as_uint(wf.x), bh1 = __float_as_uint(wf.y);
                uint32_t bl0 = __float_as_uint(wf.z), bl1 = __float_as_uint(wf.w);
                mma_tf32(acc[0][j], ahi[0], bh0, bh1);
                mma_tf32(acc[0][j], ahi[0], bl0, bl1);
                mma_tf32(acc[0][j], alo[0], bh0, bh1);
                mma_tf32(acc[1][j], ahi[1], bh0, bh1);
                mma_tf32(acc[1][j], ahi[1], bl0, bl1);
                mma_tf32(acc[1][j], alo[1], bh0, bh1);
            }
        }
    }

    // ---- epilogue ----
    const int r0 = m0 + (wid & 3) * 32;
    const int cb = (wid >> 2) * 64;
    float ep = 0.f;
    if (WAGG) ep = 1.0f + __ldg(eps + layer);
    float dots[4] = {0.f, 0.f, 0.f, 0.f};

#pragma unroll
    for (int m = 0; m < 2; m++) {
#pragma unroll
        for (int rh = 0; rh < 2; rh++) {
            int row = r0 + m * 16 + rh * 8 + (lid >> 2);
            if (row < M) {
                float dv = 0.f;
#pragma unroll
                for (int j = 0; j < 8; j++) {
                    int c = cb + j * 8 + (lid & 3) * 2;
                    float2 o;
                    o.x = acc[m][j][rh * 2 + 0] + sBias[c];
                    o.y = acc[m][j][rh * 2 + 1] + sBias[c + 1];
                    if (RELU) { o.x = fmaxf(o.x, 0.f); o.y = fmaxf(o.y, 0.f); }
                    *(float2*)(C + (size_t)row * H + c) = o;
                    if (WAGG) {
                        float2 a2;
                        a2.x = o.x * ep; a2.y = o.y * ep;
                        *(float2*)(Agg + (size_t)row * H + c) = a2;
                    }
                    if (RDOUT) dv += o.x * sRo[c] + o.y * sRo[c + 1];
                }
                if (RDOUT) dots[m * 2 + rh] = dv;
            }
        }
    }
    if (RDOUT) {
#pragma unroll
        for (int s = 0; s < 4; s++) {
            float v = dots[s];
            v += __shfl_xor_sync(0xffffffff, v, 1);
            v += __shfl_xor_sync(0xffffffff, v, 2);
            int row = r0 + (s >> 1) * 16 + (s & 1) * 8 + (lid >> 2);
            if ((lid & 3) == 0 && row < M) {
                if (cb == 0) v += __ldg(ro_b);
                atomicAdd(gout + __ldg(batch + row), v);
            }
        }
    }
}

// ---------------- launcher ------------------------------------------------------
extern "C" void kernel_launch(void* const* d_in, const int* in_sizes, int n_in,
                              void* d_out, int out_size) {
    const int*   x      = (const int*)d_in[0];
    const int*   ei     = (const int*)d_in[1];
    const int*   batch  = (const int*)d_in[2];
    const float* table  = (const float*)d_in[3];
    const float* bn_g   = (const float*)d_in[4];
    const float* bn_b   = (const float*)d_in[5];
    const float* bn_m   = (const float*)d_in[6];
    const float* bn_v   = (const float*)d_in[7];
    const float* lin_w  = (const float*)d_in[8];
    const float* lin_b  = (const float*)d_in[9];
    const float* eps    = (const float*)d_in[10];
    const float* mlp_w1 = (const float*)d_in[11];
    const float* mlp_b1 = (const float*)d_in[12];
    const float* mbn_g  = (const float*)d_in[13];
    const float* mbn_b  = (const float*)d_in[14];
    const float* mbn_m  = (const float*)d_in[15];
    const float* mbn_v  = (const float*)d_in[16];
    const float* mlp_w2 = (const float*)d_in[17];
    const float* mlp_b2 = (const float*)d_in[18];
    const float* ro_w   = (const float*)d_in[19];
    const float* ro_b   = (const float*)d_in[20];

    const int Nn = in_sizes[0];
    const int Ee = in_sizes[1] / 2;
    const int Gg = out_size;

    float *h, *t, *agg, *bf;
    float4* Wf;
    cudaGetSymbolAddress((void**)&h,   g_h);
    cudaGetSymbolAddress((void**)&t,   g_t);
    cudaGetSymbolAddress((void**)&agg, g_agg);
    cudaGetSymbolAddress((void**)&Wf,  g_Wfrag);
    cudaGetSymbolAddress((void**)&bf,  g_bf);

    const int gemm_grid = (Nn + 127) / 128;
    const int edge_grid = ((Ee * 32) + 255) / 256;

    zero_out_kernel<<<(Gg + 255) / 256, 256>>>((float*)d_out, Gg);
    fold_all_kernel<<<9, H>>>(bn_g, bn_b, bn_m, bn_v, lin_w, lin_b,
                              mbn_g, mbn_b, mbn_m, mbn_v, mlp_w1, mlp_b1,
                              mlp_w2, mlp_b2, Wf, bf);

    for (int l = 0; l < 3; l++) {
        const float4* W1 = Wf + (size_t)(3 * l + 0) * 16 * 16 * 32;
        const float4* W2 = Wf + (size_t)(3 * l + 1) * 16 * 16 * 32;
        const float4* W3 = Wf + (size_t)(3 * l + 2) * 16 * 16 * 32;
        const float* b1 = bf + (3 * l + 0) * H;
        const float* b2 = bf + (3 * l + 1) * H;
        const float* b3 = bf + (3 * l + 2) * H;

        // t := relu(BN(h) @ lin + b); agg := (1+eps)*t   (fused)
        if (l == 0)
            gemm_mma<true, true, false, true><<<gemm_grid, 256>>>(
                table, x, W1, b1, t, agg, eps, l, nullptr, nullptr, nullptr, nullptr, Nn);
        else
            gemm_mma<true, true, false, false><<<gemm_grid, 256>>>(
                h, nullptr, W1, b1, t, agg, eps, l, nullptr, nullptr, nullptr, nullptr, Nn);

        // agg += scatter_sum(t[src] -> dst)
        scatter_kernel<<<edge_grid, 256>>>(t, ei, agg, Ee);

        // t := relu(BN(agg @ mlp_w1 + b1))
        gemm_mma<true, false, false, false><<<gemm_grid, 256>>>(
            agg, nullptr, W2, b2, t, nullptr, nullptr, 0, nullptr, nullptr, nullptr, nullptr, Nn);

        // h := t @ mlp_w2 + b2  (+ fused readout on last layer)
        if (l == 2)
            gemm_mma<false, false, true, false><<<gemm_grid, 256>>>(
                t, nullptr, W3, b3, h, nullptr, nullptr, 0,
                batch, ro_w, ro_b, (float*)d_out, Nn);
        else
            gemm_mma<false, false, false, false><<<gemm_grid, 256>>>(
                t, nullptr, W3, b3, h, nullptr, nullptr, 0,
                nullptr, nullptr, nullptr, nullptr, Nn);
    }
}

// round 6
// speedup vs baseline: 2.3634x; 2.3634x over previous
#include <cuda_runtime.h>
#include <cuda_bf16.h>
#include <cstdint>

#define H 128
#define MAXN 50000
#define MAXE 800000
#define BN_EPS 1e-5f

// ---------------- device scratch ---------------------------------------------
__device__ float g_h[MAXN * H];
__device__ float g_t[MAXN * H];
__device__ float g_agg[MAXN * H];
// W fragments: [slot(9)][J(16)][katom(8)][lane(32)] = (bh0, bh1, bl0, bl1)
__device__ uint4 g_Wfrag[9 * 16 * 8 * 32];
__device__ float g_bf[9 * H];
// CSR scratch
__device__ int g_cnt[MAXN];
__device__ int g_tmp[MAXN];
__device__ int g_rowptr[MAXN + 1];
__device__ int g_csr_src[MAXE];
__device__ int g_bsum[64];

// ---------------- helpers -------------------------------------------------------
__device__ __forceinline__ uint32_t smem_addr_u32(const void* p) {
    uint32_t a;
    asm("{ .reg .u64 t; cvta.to.shared.u64 t, %1; cvt.u32.u64 %0, t; }" : "=r"(a) : "l"(p));
    return a;
}
__device__ __forceinline__ uint32_t pack_bf16x2(float a, float b) {
    uint32_t ua = (uint32_t)__bfloat16_as_ushort(__float2bfloat16_rn(a));
    uint32_t ub = (uint32_t)__bfloat16_as_ushort(__float2bfloat16_rn(b));
    return ua | (ub << 16);
}
// D += A(16x16 bf16 row) * B(16x8 bf16 col), fp32 accum
__device__ __forceinline__ void mma_bf16(float* d, const uint32_t* a,
                                         uint32_t b0, uint32_t b1) {
    asm volatile(
        "mma.sync.aligned.m16n8k16.row.col.f32.bf16.bf16.f32 "
        "{%0,%1,%2,%3}, {%4,%5,%6,%7}, {%8,%9}, {%0,%1,%2,%3};"
        : "+f"(d[0]), "+f"(d[1]), "+f"(d[2]), "+f"(d[3])
        : "r"(a[0]), "r"(a[1]), "r"(a[2]), "r"(a[3]), "r"(b0), "r"(b1));
}
__device__ __forceinline__ void ldmatrix_x4(uint32_t* r, uint32_t addr) {
    asm volatile("ldmatrix.sync.aligned.m8n8.x4.shared.b16 {%0,%1,%2,%3}, [%4];"
                 : "=r"(r[0]), "=r"(r[1]), "=r"(r[2]), "=r"(r[3]) : "r"(addr));
}

// ---------------- small kernels -------------------------------------------------
__global__ void zero_out_kernel(float* out, int n) {
    int i = blockIdx.x * blockDim.x + threadIdx.x;
    if (i < n) out[i] = 0.0f;
}
__global__ void zero_csr_kernel(int n) {
    int i = blockIdx.x * blockDim.x + threadIdx.x;
    if (i < n) { g_cnt[i] = 0; g_tmp[i] = 0; }
}
__global__ void hist_kernel(const int* __restrict__ ei, int Ee) {
    int e = blockIdx.x * blockDim.x + threadIdx.x;
    if (e >= Ee) return;
    atomicAdd(&g_cnt[__ldg(ei + Ee + e)], 1);
}
// per-block inclusive scan (1024 elems/block)
__global__ void scan_block_kernel(int n) {
    __shared__ int sh[1024];
    int gid = blockIdx.x * 1024 + threadIdx.x;
    int v = (gid < n) ? g_cnt[gid] : 0;
    sh[threadIdx.x] = v;
    __syncthreads();
    for (int off = 1; off < 1024; off <<= 1) {
        int t = (threadIdx.x >= off) ? sh[threadIdx.x - off] : 0;
        __syncthreads();
        sh[threadIdx.x] += t;
        __syncthreads();
    }
    if (gid < n) g_cnt[gid] = sh[threadIdx.x];   // in-place inclusive
    if (threadIdx.x == 1023) g_bsum[blockIdx.x] = sh[1023];
}
__global__ void scan_bsum_kernel(int nb) {
    if (threadIdx.x == 0) {
        int acc = 0;
        for (int i = 0; i < nb; i++) { int t = g_bsum[i]; g_bsum[i] = acc; acc += t; }
    }
}
__global__ void scan_final_kernel(int n) {
    int gid = blockIdx.x * 1024 + threadIdx.x;
    if (gid < n) g_rowptr[gid + 1] = g_cnt[gid] + g_bsum[blockIdx.x];
    if (gid == 0) g_rowptr[0] = 0;
}
__global__ void fill_csr_kernel(const int* __restrict__ ei, int Ee) {
    int e = blockIdx.x * blockDim.x + threadIdx.x;
    if (e >= Ee) return;
    int src = __ldg(ei + e);
    int dst = __ldg(ei + Ee + e);
    int pos = g_rowptr[dst] + atomicAdd(&g_tmp[dst], 1);
    g_csr_src[pos] = src;
}
// warp per node: agg[n] += sum_{e in CSR[n]} feat[src_e]
__global__ void gather_kernel(const float* __restrict__ feat,
                              float* __restrict__ agg, int Nn) {
    int n = (blockIdx.x * blockDim.x + threadIdx.x) >> 5;
    int lane = threadIdx.x & 31;
    if (n >= Nn) return;
    int s = g_rowptr[n], e = g_rowptr[n + 1];
    float4 acc = *(float4*)(agg + (size_t)n * H + lane * 4);
    int i = s;
    for (; i + 1 < e; i += 2) {
        int s0 = __ldg(g_csr_src + i);
        int s1 = __ldg(g_csr_src + i + 1);
        float4 v0 = *(const float4*)(feat + (size_t)s0 * H + lane * 4);
        float4 v1 = *(const float4*)(feat + (size_t)s1 * H + lane * 4);
        acc.x += v0.x + v1.x; acc.y += v0.y + v1.y;
        acc.z += v0.z + v1.z; acc.w += v0.w + v1.w;
    }
    if (i < e) {
        int s0 = __ldg(g_csr_src + i);
        float4 v0 = *(const float4*)(feat + (size_t)s0 * H + lane * 4);
        acc.x += v0.x; acc.y += v0.y; acc.z += v0.z; acc.w += v0.w;
    }
    *(float4*)(agg + (size_t)n * H + lane * 4) = acc;
}

// Fold BN into weights AND pack bf16 hi/lo mma B-fragments.
// slot = 3*layer + {0: pre-BN lin, 1: post-BN mlp_w1, 2: mlp_w2}
__global__ void fold_all_kernel(
    const float* __restrict__ bn_g, const float* __restrict__ bn_b,
    const float* __restrict__ bn_m, const float* __restrict__ bn_v,
    const float* __restrict__ lin_w, const float* __restrict__ lin_b,
    const float* __restrict__ mbn_g, const float* __restrict__ mbn_b,
    const float* __restrict__ mbn_m, const float* __restrict__ mbn_v,
    const float* __restrict__ mlp_w1, const float* __restrict__ mlp_b1,
    const float* __restrict__ mlp_w2, const float* __restrict__ mlp_b2,
    uint4* __restrict__ Wf, float* __restrict__ bo) {
    const int slot = blockIdx.x;       // 0..8
    const int l = slot / 3;
    const int type = slot % 3;
    const int n = threadIdx.x;         // output channel

    __shared__ float ss[H], st[H];
    float sv = 1.0f, tv = 0.0f;
    if (type == 0) {
        float s = bn_g[l * H + n] * rsqrtf(bn_v[l * H + n] + BN_EPS);
        ss[n] = s;
        st[n] = bn_b[l * H + n] - bn_m[l * H + n] * s;
        __syncthreads();
    } else if (type == 1) {
        sv = mbn_g[l * H + n] * rsqrtf(mbn_v[l * H + n] + BN_EPS);
        tv = mbn_b[l * H + n] - mbn_m[l * H + n] * sv;
    }

    const float* W;
    if (type == 0)      W = lin_w  + (size_t)l * H * H;
    else if (type == 1) W = mlp_w1 + (size_t)l * H * H;
    else                W = mlp_w2 + (size_t)l * H * H;

    float bias_acc;
    if (type == 0)      bias_acc = lin_b[l * H + n];
    else if (type == 1) bias_acc = mlp_b1[l * H + n] * sv + tv;
    else                bias_acc = mlp_b2[l * H + n];

    float fw[H];
    for (int cc = 0; cc < H; cc++) {
        float w = W[cc * H + n];
        float v;
        if (type == 0) { v = ss[cc] * w; bias_acc += st[cc] * w; }
        else if (type == 1) v = w * sv;
        else v = w;
        fw[cc] = v;
    }
    bo[slot * H + n] = bias_acc;

    const int J = n >> 3;
    const int g = n & 7;
    for (int katom = 0; katom < 8; katom++) {
        int k0 = katom * 16;
#pragma unroll
        for (int tg = 0; tg < 4; tg++) {
            float v00 = fw[k0 + tg * 2],     v01 = fw[k0 + tg * 2 + 1];
            float v10 = fw[k0 + tg * 2 + 8], v11 = fw[k0 + tg * 2 + 9];
            float h00 = __bfloat162float(__float2bfloat16_rn(v00));
            float h01 = __bfloat162float(__float2bfloat16_rn(v01));
            float h10 = __bfloat162float(__float2bfloat16_rn(v10));
            float h11 = __bfloat162float(__float2bfloat16_rn(v11));
            uint4 out;
            out.x = pack_bf16x2(h00, h01);
            out.y = pack_bf16x2(h10, h11);
            out.z = pack_bf16x2(v00 - h00, v01 - h01);
            out.w = pack_bf16x2(v10 - h10, v11 - h11);
            int lane = g * 4 + tg;
            Wf[(((size_t)slot * 16 + J) * 8 + katom) * 32 + lane] = out;
        }
    }
}

// ---------------- mma.sync bf16-split GEMM: C[M,128] = op(A[M,128] @ W + b) ----
// CTA: 128x128, 8 warps (4 row-blocks x 2 col-halves); warp: 32 rows x 64 cols.
// K = 8 katoms of m16n8k16; 3 products (hh, hl, lh) per mma position.
#define AW 136   // bf16 per padded smem row (272 B -> 4-bank row offset)
static constexpr int SM_AHI  = 0;
static constexpr int SM_ALO  = 128 * AW * 2;           // 34816
static constexpr int SM_BIAS = 2 * 128 * AW * 2;       // 69632
static constexpr int SM_RO   = SM_BIAS + 512;
static constexpr int SM_TOTAL_G = SM_RO + 512;         // 70656

template <bool RELU, bool WAGG, bool RDOUT, bool GATH>
__global__ void __launch_bounds__(256, 2)
gemm_bf16(const float* __restrict__ A, const int* __restrict__ gather,
          const uint4* __restrict__ Wf, const float* __restrict__ bias,
          float* __restrict__ C, float* __restrict__ Agg,
          const float* __restrict__ eps, int layer,
          const int* __restrict__ batch, const float* __restrict__ ro_w,
          const float* __restrict__ ro_b, float* __restrict__ gout, int M) {
    extern __shared__ char smem[];
    __nv_bfloat16* sAhi = (__nv_bfloat16*)(smem + SM_AHI);
    __nv_bfloat16* sAlo = (__nv_bfloat16*)(smem + SM_ALO);
    float* sBias = (float*)(smem + SM_BIAS);
    float* sRo   = (float*)(smem + SM_RO);

    const int tid = threadIdx.x;
    const int wid = tid >> 5, lid = tid & 31;
    const int m0 = blockIdx.x * 128;
    const int J0 = (wid >> 2) * 8;

    if (tid < H) {
        sBias[tid] = bias[tid];
        if (RDOUT) sRo[tid] = ro_w[tid];
    }

    // ---- stage whole A tile [128 x 128] as bf16 hi/lo ----
#pragma unroll
    for (int i = 0; i < 16; i++) {
        int idx = tid + i * 256;            // 0..4095 float4 tasks
        int row = idx >> 5;
        int c4  = idx & 31;
        int m = m0 + row;
        float4 v = make_float4(0.f, 0.f, 0.f, 0.f);
        if (m < M) {
            const float* src;
            if (GATH) src = A + (size_t)__ldg(gather + m) * H;
            else      src = A + (size_t)m * H;
            v = *(const float4*)(src + c4 * 4);
        }
        float hx = __bfloat162float(__float2bfloat16_rn(v.x));
        float hy = __bfloat162float(__float2bfloat16_rn(v.y));
        float hz = __bfloat162float(__float2bfloat16_rn(v.z));
        float hw = __bfloat162float(__float2bfloat16_rn(v.w));
        uint2 hpack, lpack;
        hpack.x = pack_bf16x2(hx, hy);
        hpack.y = pack_bf16x2(hz, hw);
        lpack.x = pack_bf16x2(v.x - hx, v.y - hy);
        lpack.y = pack_bf16x2(v.z - hz, v.w - hw);
        *(uint2*)&sAhi[row * AW + c4 * 4] = hpack;
        *(uint2*)&sAlo[row * AW + c4 * 4] = lpack;
    }
    __syncthreads();

    float acc[2][8][4];
#pragma unroll
    for (int m = 0; m < 2; m++)
#pragma unroll
        for (int j = 0; j < 8; j++)
#pragma unroll
            for (int r = 0; r < 4; r++) acc[m][j][r] = 0.0f;

    const int R = (wid & 3) * 32;
    // ldmatrix lane addressing: row = base + (lid&7) + ((lid>>3)&1)*8, col += (lid>>4)*8
    const int lrow = (lid & 7) + ((lid >> 3) & 1) * 8;
    const int lcol = (lid >> 4) * 8;
    const uint32_t aHiBase = smem_addr_u32(sAhi);
    const uint32_t aLoBase = smem_addr_u32(sAlo);

#pragma unroll
    for (int katom = 0; katom < 8; katom++) {
        const int k0 = katom * 16;
        uint32_t ahi[2][4], alo[2][4];
#pragma unroll
        for (int m = 0; m < 2; m++) {
            uint32_t off = (uint32_t)((R + m * 16 + lrow) * AW + k0 + lcol) * 2;
            ldmatrix_x4(ahi[m], aHiBase + off);
            ldmatrix_x4(alo[m], aLoBase + off);
        }
#pragma unroll
        for (int j = 0; j < 8; j++) {
            uint4 wf = __ldg(&Wf[(((size_t)(J0 + j)) * 8 + katom) * 32 + lid]);
            mma_bf16(acc[0][j], ahi[0], wf.x, wf.y);
            mma_bf16(acc[0][j], ahi[0], wf.z, wf.w);
            mma_bf16(acc[0][j], alo[0], wf.x, wf.y);
            mma_bf16(acc[1][j], ahi[1], wf.x, wf.y);
            mma_bf16(acc[1][j], ahi[1], wf.z, wf.w);
            mma_bf16(acc[1][j], alo[1], wf.x, wf.y);
        }
    }

    // ---- epilogue: lane (g = lid>>2 rows, tg = lid&3 col-pairs) ----
    const int r0 = m0 + R;
    const int cb = (wid >> 2) * 64;
    const int g = lid >> 2, tg = lid & 3;
    float ep = 0.f;
    if (WAGG) ep = 1.0f + __ldg(eps + layer);
    float dots[4] = {0.f, 0.f, 0.f, 0.f};

#pragma unroll
    for (int m = 0; m < 2; m++) {
#pragma unroll
        for (int rh = 0; rh < 2; rh++) {
            int row = r0 + m * 16 + rh * 8 + g;
            if (row < M) {
                float dv = 0.f;
#pragma unroll
                for (int j = 0; j < 8; j++) {
                    int c = cb + j * 8 + tg * 2;
                    float2 o;
                    o.x = acc[m][j][rh * 2 + 0] + sBias[c];
                    o.y = acc[m][j][rh * 2 + 1] + sBias[c + 1];
                    if (RELU) { o.x = fmaxf(o.x, 0.f); o.y = fmaxf(o.y, 0.f); }
                    *(float2*)(C + (size_t)row * H + c) = o;
                    if (WAGG) {
                        float2 a2;
                        a2.x = o.x * ep; a2.y = o.y * ep;
                        *(float2*)(Agg + (size_t)row * H + c) = a2;
                    }
                    if (RDOUT) dv += o.x * sRo[c] + o.y * sRo[c + 1];
                }
                if (RDOUT) dots[m * 2 + rh] = dv;
            }
        }
    }
    if (RDOUT) {
#pragma unroll
        for (int s = 0; s < 4; s++) {
            float v = dots[s];
            v += __shfl_xor_sync(0xffffffff, v, 1);
            v += __shfl_xor_sync(0xffffffff, v, 2);
            int row = r0 + (s >> 1) * 16 + (s & 1) * 8 + g;
            if (tg == 0 && row < M) {
                if (cb == 0) v += __ldg(ro_b);
                atomicAdd(gout + __ldg(batch + row), v);
            }
        }
    }
}

// ---------------- launcher ------------------------------------------------------
extern "C" void kernel_launch(void* const* d_in, const int* in_sizes, int n_in,
                              void* d_out, int out_size) {
    const int*   x      = (const int*)d_in[0];
    const int*   ei     = (const int*)d_in[1];
    const int*   batch  = (const int*)d_in[2];
    const float* table  = (const float*)d_in[3];
    const float* bn_g   = (const float*)d_in[4];
    const float* bn_b   = (const float*)d_in[5];
    const float* bn_m   = (const float*)d_in[6];
    const float* bn_v   = (const float*)d_in[7];
    const float* lin_w  = (const float*)d_in[8];
    const float* lin_b  = (const float*)d_in[9];
    const float* eps    = (const float*)d_in[10];
    const float* mlp_w1 = (const float*)d_in[11];
    const float* mlp_b1 = (const float*)d_in[12];
    const float* mbn_g  = (const float*)d_in[13];
    const float* mbn_b  = (const float*)d_in[14];
    const float* mbn_m  = (const float*)d_in[15];
    const float* mbn_v  = (const float*)d_in[16];
    const float* mlp_w2 = (const float*)d_in[17];
    const float* mlp_b2 = (const float*)d_in[18];
    const float* ro_w   = (const float*)d_in[19];
    const float* ro_b   = (const float*)d_in[20];

    const int Nn = in_sizes[0];
    const int Ee = in_sizes[1] / 2;
    const int Gg = out_size;

    float *h, *t, *agg, *bf;
    uint4* Wf;
    cudaGetSymbolAddress((void**)&h,   g_h);
    cudaGetSymbolAddress((void**)&t,   g_t);
    cudaGetSymbolAddress((void**)&agg, g_agg);
    cudaGetSymbolAddress((void**)&Wf,  g_Wfrag);
    cudaGetSymbolAddress((void**)&bf,  g_bf);

    cudaFuncSetAttribute(gemm_bf16<true,  true,  false, true >, cudaFuncAttributeMaxDynamicSharedMemorySize, SM_TOTAL_G);
    cudaFuncSetAttribute(gemm_bf16<true,  true,  false, false>, cudaFuncAttributeMaxDynamicSharedMemorySize, SM_TOTAL_G);
    cudaFuncSetAttribute(gemm_bf16<true,  false, false, false>, cudaFuncAttributeMaxDynamicSharedMemorySize, SM_TOTAL_G);
    cudaFuncSetAttribute(gemm_bf16<false, false, false, false>, cudaFuncAttributeMaxDynamicSharedMemorySize, SM_TOTAL_G);
    cudaFuncSetAttribute(gemm_bf16<false, false, true,  false>, cudaFuncAttributeMaxDynamicSharedMemorySize, SM_TOTAL_G);

    const int gemm_grid = (Nn + 127) / 128;
    const int edge_grid = (Ee + 255) / 256;
    const int node_grid = (Nn + 1023) / 1024;   // for 1024-wide scan blocks
    const int warp_grid = ((Nn * 32) + 255) / 256;

    // ---- output zero + CSR build (once per launch) ----
    zero_out_kernel<<<(Gg + 255) / 256, 256>>>((float*)d_out, Gg);
    zero_csr_kernel<<<(Nn + 255) / 256, 256>>>(Nn);
    hist_kernel<<<edge_grid, 256>>>(ei, Ee);
    scan_block_kernel<<<node_grid, 1024>>>(Nn);
    scan_bsum_kernel<<<1, 32>>>(node_grid);
    scan_final_kernel<<<node_grid, 1024>>>(Nn);
    fill_csr_kernel<<<edge_grid, 256>>>(ei, Ee);

    fold_all_kernel<<<9, H>>>(bn_g, bn_b, bn_m, bn_v, lin_w, lin_b,
                              mbn_g, mbn_b, mbn_m, mbn_v, mlp_w1, mlp_b1,
                              mlp_w2, mlp_b2, Wf, bf);

    for (int l = 0; l < 3; l++) {
        const uint4* W1 = Wf + (size_t)(3 * l + 0) * 16 * 8 * 32;
        const uint4* W2 = Wf + (size_t)(3 * l + 1) * 16 * 8 * 32;
        const uint4* W3 = Wf + (size_t)(3 * l + 2) * 16 * 8 * 32;
        const float* b1 = bf + (3 * l + 0) * H;
        const float* b2 = bf + (3 * l + 1) * H;
        const float* b3 = bf + (3 * l + 2) * H;

        // t := relu(BN(h) @ lin + b); agg := (1+eps)*t   (fused)
        if (l == 0)
            gemm_bf16<true, true, false, true><<<gemm_grid, 256, SM_TOTAL_G>>>(
                table, x, W1, b1, t, agg, eps, l, nullptr, nullptr, nullptr, nullptr, Nn);
        else
            gemm_bf16<true, true, false, false><<<gemm_grid, 256, SM_TOTAL_G>>>(
                h, nullptr, W1, b1, t, agg, eps, l, nullptr, nullptr, nullptr, nullptr, Nn);

        // agg[n] += sum over CSR neighbors of t
        gather_kernel<<<warp_grid, 256>>>(t, agg, Nn);

        // t := relu(BN(agg @ mlp_w1 + b1))
        gemm_bf16<true, false, false, false><<<gemm_grid, 256, SM_TOTAL_G>>>(
            agg, nullptr, W2, b2, t, nullptr, nullptr, 0, nullptr, nullptr, nullptr, nullptr, Nn);

        // h := t @ mlp_w2 + b2  (+ fused readout on last layer)
        if (l == 2)
            gemm_bf16<false, false, true, false><<<gemm_grid, 256, SM_TOTAL_G>>>(
                t, nullptr, W3, b3, h, nullptr, nullptr, 0,
                batch, ro_w, ro_b, (float*)d_out, Nn);
        else
            gemm_bf16<false, false, false, false><<<gemm_grid, 256, SM_TOTAL_G>>>(
                t, nullptr, W3, b3, h, nullptr, nullptr, 0,
                nullptr, nullptr, nullptr, nullptr, Nn);
    }
}

// round 7
// speedup vs baseline: 2.7738x; 1.1736x over previous
#include <cuda_runtime.h>
#include <cuda_bf16.h>
#include <cstdint>

#define H 128
#define MAXN 50000
#define MAXE 800000
#define BN_EPS 1e-5f

// ---------------- device scratch ---------------------------------------------
__device__ float g_h[MAXN * H];
__device__ float g_t[MAXN * H];
__device__ float g_agg[MAXN * H];
// W fragments: [slot(9)][J(16)][katom(8)][lane(32)] = (bh0, bh1, bl0, bl1)
__device__ uint4 g_Wfrag[9 * 16 * 8 * 32];
__device__ float g_bf[9 * H];
// CSR scratch
__device__ int g_cnt[MAXN];
__device__ int g_tmp[MAXN];
__device__ int g_rowptr[MAXN + 1];
__device__ int g_csr_src[MAXE];
__device__ int g_bsum[64];

// ---------------- helpers -------------------------------------------------------
__device__ __forceinline__ uint32_t smem_addr_u32(const void* p) {
    uint32_t a;
    asm("{ .reg .u64 t; cvta.to.shared.u64 t, %1; cvt.u32.u64 %0, t; }" : "=r"(a) : "l"(p));
    return a;
}
__device__ __forceinline__ uint32_t pack_bf16x2(float a, float b) {
    uint32_t ua = (uint32_t)__bfloat16_as_ushort(__float2bfloat16_rn(a));
    uint32_t ub = (uint32_t)__bfloat16_as_ushort(__float2bfloat16_rn(b));
    return ua | (ub << 16);
}
__device__ __forceinline__ float bf16_rt(float x) {
    return __bfloat162float(__float2bfloat16_rn(x));
}
// D += A(16x16 bf16 row) * B(16x8 bf16 col), fp32 accum
__device__ __forceinline__ void mma_bf16(float* d, const uint32_t* a,
                                         uint32_t b0, uint32_t b1) {
    asm volatile(
        "mma.sync.aligned.m16n8k16.row.col.f32.bf16.bf16.f32 "
        "{%0,%1,%2,%3}, {%4,%5,%6,%7}, {%8,%9}, {%0,%1,%2,%3};"
        : "+f"(d[0]), "+f"(d[1]), "+f"(d[2]), "+f"(d[3])
        : "r"(a[0]), "r"(a[1]), "r"(a[2]), "r"(a[3]), "r"(b0), "r"(b1));
}
__device__ __forceinline__ void ldmatrix_x4(uint32_t* r, uint32_t addr) {
    asm volatile("ldmatrix.sync.aligned.m8n8.x4.shared.b16 {%0,%1,%2,%3}, [%4];"
                 : "=r"(r[0]), "=r"(r[1]), "=r"(r[2]), "=r"(r[3]) : "r"(addr));
}

// ---------------- small kernels -------------------------------------------------
__global__ void zero_out_kernel(float* out, int n) {
    int i = blockIdx.x * blockDim.x + threadIdx.x;
    if (i < n) out[i] = 0.0f;
}
__global__ void zero_csr_kernel(int n) {
    int i = blockIdx.x * blockDim.x + threadIdx.x;
    if (i < n) { g_cnt[i] = 0; g_tmp[i] = 0; }
}
__global__ void hist_kernel(const int* __restrict__ ei, int Ee) {
    int e = blockIdx.x * blockDim.x + threadIdx.x;
    if (e >= Ee) return;
    atomicAdd(&g_cnt[__ldg(ei + Ee + e)], 1);
}
__global__ void scan_block_kernel(int n) {
    __shared__ int sh[1024];
    int gid = blockIdx.x * 1024 + threadIdx.x;
    int v = (gid < n) ? g_cnt[gid] : 0;
    sh[threadIdx.x] = v;
    __syncthreads();
    for (int off = 1; off < 1024; off <<= 1) {
        int t = (threadIdx.x >= off) ? sh[threadIdx.x - off] : 0;
        __syncthreads();
        sh[threadIdx.x] += t;
        __syncthreads();
    }
    if (gid < n) g_cnt[gid] = sh[threadIdx.x];
    if (threadIdx.x == 1023) g_bsum[blockIdx.x] = sh[1023];
}
__global__ void scan_bsum_kernel(int nb) {
    if (threadIdx.x == 0) {
        int acc = 0;
        for (int i = 0; i < nb; i++) { int t = g_bsum[i]; g_bsum[i] = acc; acc += t; }
    }
}
__global__ void scan_final_kernel(int n) {
    int gid = blockIdx.x * 1024 + threadIdx.x;
    if (gid < n) g_rowptr[gid + 1] = g_cnt[gid] + g_bsum[blockIdx.x];
    if (gid == 0) g_rowptr[0] = 0;
}
__global__ void fill_csr_kernel(const int* __restrict__ ei, int Ee) {
    int e = blockIdx.x * blockDim.x + threadIdx.x;
    if (e >= Ee) return;
    int src = __ldg(ei + e);
    int dst = __ldg(ei + Ee + e);
    int pos = g_rowptr[dst] + atomicAdd(&g_tmp[dst], 1);
    g_csr_src[pos] = src;
}
// warp per node: agg[n] = (1+eps)*feat[n] + sum_{e in CSR[n]} feat[src_e]
__global__ void gather_kernel(const float* __restrict__ feat,
                              const float* __restrict__ eps, int layer,
                              float* __restrict__ agg, int Nn) {
    int n = (blockIdx.x * blockDim.x + threadIdx.x) >> 5;
    int lane = threadIdx.x & 31;
    if (n >= Nn) return;
    float sc = 1.0f + __ldg(eps + layer);
    float4 self = *(const float4*)(feat + (size_t)n * H + lane * 4);
    float4 acc;
    acc.x = self.x * sc; acc.y = self.y * sc;
    acc.z = self.z * sc; acc.w = self.w * sc;
    int s = g_rowptr[n], e = g_rowptr[n + 1];
    int i = s;
    for (; i + 3 < e; i += 4) {
        int s0 = __ldg(g_csr_src + i);
        int s1 = __ldg(g_csr_src + i + 1);
        int s2 = __ldg(g_csr_src + i + 2);
        int s3 = __ldg(g_csr_src + i + 3);
        float4 v0 = *(const float4*)(feat + (size_t)s0 * H + lane * 4);
        float4 v1 = *(const float4*)(feat + (size_t)s1 * H + lane * 4);
        float4 v2 = *(const float4*)(feat + (size_t)s2 * H + lane * 4);
        float4 v3 = *(const float4*)(feat + (size_t)s3 * H + lane * 4);
        acc.x += (v0.x + v1.x) + (v2.x + v3.x);
        acc.y += (v0.y + v1.y) + (v2.y + v3.y);
        acc.z += (v0.z + v1.z) + (v2.z + v3.z);
        acc.w += (v0.w + v1.w) + (v2.w + v3.w);
    }
    for (; i < e; i++) {
        int s0 = __ldg(g_csr_src + i);
        float4 v0 = *(const float4*)(feat + (size_t)s0 * H + lane * 4);
        acc.x += v0.x; acc.y += v0.y; acc.z += v0.z; acc.w += v0.w;
    }
    *(float4*)(agg + (size_t)n * H + lane * 4) = acc;
}

// Fold BN into weights AND pack bf16 hi/lo mma B-fragments (no local arrays).
// slot = 3*layer + {0: pre-BN lin, 1: post-BN mlp_w1, 2: mlp_w2}
__global__ void fold_all_kernel(
    const float* __restrict__ bn_g, const float* __restrict__ bn_b,
    const float* __restrict__ bn_m, const float* __restrict__ bn_v,
    const float* __restrict__ lin_w, const float* __restrict__ lin_b,
    const float* __restrict__ mbn_g, const float* __restrict__ mbn_b,
    const float* __restrict__ mbn_m, const float* __restrict__ mbn_v,
    const float* __restrict__ mlp_w1, const float* __restrict__ mlp_b1,
    const float* __restrict__ mlp_w2, const float* __restrict__ mlp_b2,
    uint4* __restrict__ Wf, float* __restrict__ bo) {
    const int slot = blockIdx.x;       // 0..8
    const int l = slot / 3;
    const int type = slot % 3;
    const int n = threadIdx.x;         // output channel

    __shared__ float ss[H], st[H];
    float sv = 1.0f, tv = 0.0f;
    if (type == 0) {
        float s = bn_g[l * H + n] * rsqrtf(bn_v[l * H + n] + BN_EPS);
        ss[n] = s;
        st[n] = bn_b[l * H + n] - bn_m[l * H + n] * s;
        __syncthreads();
    } else if (type == 1) {
        sv = mbn_g[l * H + n] * rsqrtf(mbn_v[l * H + n] + BN_EPS);
        tv = mbn_b[l * H + n] - mbn_m[l * H + n] * sv;
    }

    const float* W;
    if (type == 0)      W = lin_w  + (size_t)l * H * H;
    else if (type == 1) W = mlp_w1 + (size_t)l * H * H;
    else                W = mlp_w2 + (size_t)l * H * H;

    float bias_acc;
    if (type == 0) {
        bias_acc = lin_b[l * H + n];
        for (int cc = 0; cc < H; cc++)
            bias_acc += st[cc] * W[cc * H + n];
    } else if (type == 1) {
        bias_acc = mlp_b1[l * H + n] * sv + tv;
    } else {
        bias_acc = mlp_b2[l * H + n];
    }
    bo[slot * H + n] = bias_acc;

    const int J = n >> 3;
    const int g = n & 7;
    for (int katom = 0; katom < 8; katom++) {
#pragma unroll
        for (int tg = 0; tg < 4; tg++) {
            int k0 = katom * 16 + tg * 2;
            float v00, v01, v10, v11;
            if (type == 0) {
                v00 = ss[k0]     * W[(k0)     * H + n];
                v01 = ss[k0 + 1] * W[(k0 + 1) * H + n];
                v10 = ss[k0 + 8] * W[(k0 + 8) * H + n];
                v11 = ss[k0 + 9] * W[(k0 + 9) * H + n];
            } else {
                v00 = W[(k0)     * H + n] * sv;
                v01 = W[(k0 + 1) * H + n] * sv;
                v10 = W[(k0 + 8) * H + n] * sv;
                v11 = W[(k0 + 9) * H + n] * sv;
            }
            float h00 = bf16_rt(v00), h01 = bf16_rt(v01);
            float h10 = bf16_rt(v10), h11 = bf16_rt(v11);
            uint4 out;
            out.x = pack_bf16x2(h00, h01);
            out.y = pack_bf16x2(h10, h11);
            out.z = pack_bf16x2(v00 - h00, v01 - h01);
            out.w = pack_bf16x2(v10 - h10, v11 - h11);
            int lane = g * 4 + tg;
            Wf[(((size_t)slot * 16 + J) * 8 + katom) * 32 + lane] = out;
        }
    }
}

// ---------------- mma.sync bf16-split GEMM: C[M,128] = op(A[M,128] @ W + b) ----
// CTA: 128x128, 8 warps (4 row-blocks x 2 col-halves); warp: 32 rows x 64 cols.
#define AW 136   // bf16 per padded smem row
static constexpr int SM_AHI  = 0;
static constexpr int SM_ALO  = 128 * AW * 2;           // 34816
static constexpr int SM_BIAS = 2 * 128 * AW * 2;       // 69632
static constexpr int SM_RO   = SM_BIAS + 512;
static constexpr int SM_TOTAL_G = SM_RO + 512;         // 70656

template <bool RELU, bool RDOUT, bool GATH>
__global__ void __launch_bounds__(256, 2)
gemm_bf16(const float* __restrict__ A, const int* __restrict__ gather,
          const uint4* __restrict__ Wf, const float* __restrict__ bias,
          float* __restrict__ C,
          const int* __restrict__ batch, const float* __restrict__ ro_w,
          const float* __restrict__ ro_b, float* __restrict__ gout, int M) {
    extern __shared__ char smem[];
    __nv_bfloat16* sAhi = (__nv_bfloat16*)(smem + SM_AHI);
    __nv_bfloat16* sAlo = (__nv_bfloat16*)(smem + SM_ALO);
    float* sBias = (float*)(smem + SM_BIAS);
    float* sRo   = (float*)(smem + SM_RO);

    const int tid = threadIdx.x;
    const int wid = tid >> 5, lid = tid & 31;
    const int m0 = blockIdx.x * 128;
    const int J0 = (wid >> 2) * 8;

    if (tid < H) {
        sBias[tid] = bias[tid];
        if (RDOUT) sRo[tid] = ro_w[tid];
    }

    // ---- stage whole A tile [128 x 128] as bf16 hi/lo ----
#pragma unroll
    for (int i = 0; i < 16; i++) {
        int idx = tid + i * 256;
        int row = idx >> 5;
        int c4  = idx & 31;
        int m = m0 + row;
        float4 v = make_float4(0.f, 0.f, 0.f, 0.f);
        if (m < M) {
            const float* src;
            if (GATH) src = A + (size_t)__ldg(gather + m) * H;
            else      src = A + (size_t)m * H;
            v = *(const float4*)(src + c4 * 4);
        }
        float hx = bf16_rt(v.x), hy = bf16_rt(v.y);
        float hz = bf16_rt(v.z), hw = bf16_rt(v.w);
        uint2 hpack, lpack;
        hpack.x = pack_bf16x2(hx, hy);
        hpack.y = pack_bf16x2(hz, hw);
        lpack.x = pack_bf16x2(v.x - hx, v.y - hy);
        lpack.y = pack_bf16x2(v.z - hz, v.w - hw);
        *(uint2*)&sAhi[row * AW + c4 * 4] = hpack;
        *(uint2*)&sAlo[row * AW + c4 * 4] = lpack;
    }
    __syncthreads();

    float acc[2][8][4];
#pragma unroll
    for (int m = 0; m < 2; m++)
#pragma unroll
        for (int j = 0; j < 8; j++)
#pragma unroll
            for (int r = 0; r < 4; r++) acc[m][j][r] = 0.0f;

    const int R = (wid & 3) * 32;
    const int lrow = (lid & 7) + ((lid >> 3) & 1) * 8;
    const int lcol = (lid >> 4) * 8;
    const uint32_t aHiBase = smem_addr_u32(sAhi);
    const uint32_t aLoBase = smem_addr_u32(sAlo);

#pragma unroll
    for (int katom = 0; katom < 8; katom++) {
        const int k0 = katom * 16;
        uint32_t ahi[2][4], alo[2][4];
#pragma unroll
        for (int m = 0; m < 2; m++) {
            uint32_t off = (uint32_t)((R + m * 16 + lrow) * AW + k0 + lcol) * 2;
            ldmatrix_x4(ahi[m], aHiBase + off);
            ldmatrix_x4(alo[m], aLoBase + off);
        }
#pragma unroll
        for (int j = 0; j < 8; j++) {
            uint4 wf = __ldg(&Wf[(((size_t)(J0 + j)) * 8 + katom) * 32 + lid]);
            // interleave m=0 / m=1 to break accumulator RAW chains
            mma_bf16(acc[0][j], ahi[0], wf.x, wf.y);
            mma_bf16(acc[1][j], ahi[1], wf.x, wf.y);
            mma_bf16(acc[0][j], ahi[0], wf.z, wf.w);
            mma_bf16(acc[1][j], ahi[1], wf.z, wf.w);
            mma_bf16(acc[0][j], alo[0], wf.x, wf.y);
            mma_bf16(acc[1][j], alo[1], wf.x, wf.y);
        }
    }

    // ---- epilogue ----
    const int r0 = m0 + R;
    const int cb = (wid >> 2) * 64;
    const int g = lid >> 2, tg = lid & 3;
    float dots[4] = {0.f, 0.f, 0.f, 0.f};

#pragma unroll
    for (int m = 0; m < 2; m++) {
#pragma unroll
        for (int rh = 0; rh < 2; rh++) {
            int row = r0 + m * 16 + rh * 8 + g;
            if (row < M) {
                float dv = 0.f;
#pragma unroll
                for (int j = 0; j < 8; j++) {
                    int c = cb + j * 8 + tg * 2;
                    float2 o;
                    o.x = acc[m][j][rh * 2 + 0] + sBias[c];
                    o.y = acc[m][j][rh * 2 + 1] + sBias[c + 1];
                    if (RELU) { o.x = fmaxf(o.x, 0.f); o.y = fmaxf(o.y, 0.f); }
                    *(float2*)(C + (size_t)row * H + c) = o;
                    if (RDOUT) dv += o.x * sRo[c] + o.y * sRo[c + 1];
                }
                if (RDOUT) dots[m * 2 + rh] = dv;
            }
        }
    }
    if (RDOUT) {
#pragma unroll
        for (int s = 0; s < 4; s++) {
            float v = dots[s];
            v += __shfl_xor_sync(0xffffffff, v, 1);
            v += __shfl_xor_sync(0xffffffff, v, 2);
            int row = r0 + (s >> 1) * 16 + (s & 1) * 8 + g;
            if (tg == 0 && row < M) {
                if (cb == 0) v += __ldg(ro_b);
                atomicAdd(gout + __ldg(batch + row), v);
            }
        }
    }
}

// ---------------- launcher ------------------------------------------------------
extern "C" void kernel_launch(void* const* d_in, const int* in_sizes, int n_in,
                              void* d_out, int out_size) {
    const int*   x      = (const int*)d_in[0];
    const int*   ei     = (const int*)d_in[1];
    const int*   batch  = (const int*)d_in[2];
    const float* table  = (const float*)d_in[3];
    const float* bn_g   = (const float*)d_in[4];
    const float* bn_b   = (const float*)d_in[5];
    const float* bn_m   = (const float*)d_in[6];
    const float* bn_v   = (const float*)d_in[7];
    const float* lin_w  = (const float*)d_in[8];
    const float* lin_b  = (const float*)d_in[9];
    const float* eps    = (const float*)d_in[10];
    const float* mlp_w1 = (const float*)d_in[11];
    const float* mlp_b1 = (const float*)d_in[12];
    const float* mbn_g  = (const float*)d_in[13];
    const float* mbn_b  = (const float*)d_in[14];
    const float* mbn_m  = (const float*)d_in[15];
    const float* mbn_v  = (const float*)d_in[16];
    const float* mlp_w2 = (const float*)d_in[17];
    const float* mlp_b2 = (const float*)d_in[18];
    const float* ro_w   = (const float*)d_in[19];
    const float* ro_b   = (const float*)d_in[20];

    const int Nn = in_sizes[0];
    const int Ee = in_sizes[1] / 2;
    const int Gg = out_size;

    float *h, *t, *agg, *bf;
    uint4* Wf;
    cudaGetSymbolAddress((void**)&h,   g_h);
    cudaGetSymbolAddress((void**)&t,   g_t);
    cudaGetSymbolAddress((void**)&agg, g_agg);
    cudaGetSymbolAddress((void**)&Wf,  g_Wfrag);
    cudaGetSymbolAddress((void**)&bf,  g_bf);

    cudaFuncSetAttribute(gemm_bf16<true,  false, true >, cudaFuncAttributeMaxDynamicSharedMemorySize, SM_TOTAL_G);
    cudaFuncSetAttribute(gemm_bf16<true,  false, false>, cudaFuncAttributeMaxDynamicSharedMemorySize, SM_TOTAL_G);
    cudaFuncSetAttribute(gemm_bf16<false, false, false>, cudaFuncAttributeMaxDynamicSharedMemorySize, SM_TOTAL_G);
    cudaFuncSetAttribute(gemm_bf16<false, true,  false>, cudaFuncAttributeMaxDynamicSharedMemorySize, SM_TOTAL_G);

    const int gemm_grid = (Nn + 127) / 128;
    const int edge_grid = (Ee + 255) / 256;
    const int node_grid = (Nn + 1023) / 1024;
    const int warp_grid = ((Nn * 32) + 255) / 256;

    // Launch order arranged so launch #4 (the ncu-captured one) is the first GEMM.
    zero_out_kernel<<<(Gg + 255) / 256, 256>>>((float*)d_out, Gg);            // 1
    zero_csr_kernel<<<(Nn + 255) / 256, 256>>>(Nn);                           // 2
    fold_all_kernel<<<9, H>>>(bn_g, bn_b, bn_m, bn_v, lin_w, lin_b,           // 3
                              mbn_g, mbn_b, mbn_m, mbn_v, mlp_w1, mlp_b1,
                              mlp_w2, mlp_b2, Wf, bf);
    // t := relu(BN(embed[x]) @ lin + b)   (layer 0, fused gather of embeddings)
    gemm_bf16<true, false, true><<<gemm_grid, 256, SM_TOTAL_G>>>(             // 4
        table, x, Wf, bf, t, nullptr, nullptr, nullptr, nullptr, Nn);
    // CSR build (independent of layer-0 GEMM)
    hist_kernel<<<edge_grid, 256>>>(ei, Ee);                                  // 5
    scan_block_kernel<<<node_grid, 1024>>>(Nn);                               // 6
    scan_bsum_kernel<<<1, 32>>>(node_grid);                                   // 7
    scan_final_kernel<<<node_grid, 1024>>>(Nn);                               // 8
    fill_csr_kernel<<<edge_grid, 256>>>(ei, Ee);                              // 9

    for (int l = 0; l < 3; l++) {
        const uint4* W1 = Wf + (size_t)(3 * l + 0) * 16 * 8 * 32;
        const uint4* W2 = Wf + (size_t)(3 * l + 1) * 16 * 8 * 32;
        const uint4* W3 = Wf + (size_t)(3 * l + 2) * 16 * 8 * 32;
        const float* b1 = bf + (3 * l + 0) * H;
        const float* b2 = bf + (3 * l + 1) * H;
        const float* b3 = bf + (3 * l + 2) * H;

        // t := relu(BN(h) @ lin + b)   (layer 0 already issued above)
        if (l > 0)
            gemm_bf16<true, false, false><<<gemm_grid, 256, SM_TOTAL_G>>>(
                h, nullptr, W1, b1, t, nullptr, nullptr, nullptr, nullptr, Nn);

        // agg[n] := (1+eps)*t[n] + sum over CSR neighbors of t   (fused init)
        gather_kernel<<<warp_grid, 256>>>(t, eps, l, agg, Nn);

        // t := relu(BN(agg @ mlp_w1 + b1))
        gemm_bf16<true, false, false><<<gemm_grid, 256, SM_TOTAL_G>>>(
            agg, nullptr, W2, b2, t, nullptr, nullptr, nullptr, nullptr, Nn);

        // h := t @ mlp_w2 + b2  (+ fused readout on last layer)
        if (l == 2)
            gemm_bf16<false, true, false><<<gemm_grid, 256, SM_TOTAL_G>>>(
                t, nullptr, W3, b3, h, batch, ro_w, ro_b, (float*)d_out, Nn);
        else
            gemm_bf16<false, false, false><<<gemm_grid, 256, SM_TOTAL_G>>>(
                t, nullptr, W3, b3, h, nullptr, nullptr, nullptr, nullptr, Nn);
    }
}

// round 8
// speedup vs baseline: 2.9000x; 1.0455x over previous
#include <cuda_runtime.h>
#include <cuda_bf16.h>
#include <cstdint>

#define H 128
#define MAXN 50000
#define MAXE 800000
#define BN_EPS 1e-5f

// ---------------- device scratch ---------------------------------------------
__device__ float g_h[MAXN * H];
__device__ float g_t[MAXN * H];
__device__ float g_agg[MAXN * H];
// W fragments: [slot(9)][J(16)][katom(8)][lane(32)] = (bh0, bh1, bl0, bl1)
__device__ uint4 g_Wfrag[9 * 16 * 8 * 32];
__device__ float g_bf[9 * H];
// CSR scratch
__device__ int g_cnt[MAXN];
__device__ int g_tmp[MAXN];
__device__ int g_rowptr[MAXN + 1];
__device__ int g_csr_src[MAXE];
__device__ int g_bsum[64];

// ---------------- helpers -------------------------------------------------------
__device__ __forceinline__ uint32_t smem_addr_u32(const void* p) {
    uint32_t a;
    asm("{ .reg .u64 t; cvta.to.shared.u64 t, %1; cvt.u32.u64 %0, t; }" : "=r"(a) : "l"(p));
    return a;
}
__device__ __forceinline__ uint32_t pack_bf16x2(float a, float b) {
    uint32_t ua = (uint32_t)__bfloat16_as_ushort(__float2bfloat16_rn(a));
    uint32_t ub = (uint32_t)__bfloat16_as_ushort(__float2bfloat16_rn(b));
    return ua | (ub << 16);
}
__device__ __forceinline__ float bf16_rt(float x) {
    return __bfloat162float(__float2bfloat16_rn(x));
}
__device__ __forceinline__ void mma_bf16(float* d, const uint32_t* a,
                                         uint32_t b0, uint32_t b1) {
    asm volatile(
        "mma.sync.aligned.m16n8k16.row.col.f32.bf16.bf16.f32 "
        "{%0,%1,%2,%3}, {%4,%5,%6,%7}, {%8,%9}, {%0,%1,%2,%3};"
        : "+f"(d[0]), "+f"(d[1]), "+f"(d[2]), "+f"(d[3])
        : "r"(a[0]), "r"(a[1]), "r"(a[2]), "r"(a[3]), "r"(b0), "r"(b1));
}
__device__ __forceinline__ void ldmatrix_x4(uint32_t* r, uint32_t addr) {
    asm volatile("ldmatrix.sync.aligned.m8n8.x4.shared.b16 {%0,%1,%2,%3}, [%4];"
                 : "=r"(r[0]), "=r"(r[1]), "=r"(r[2]), "=r"(r[3]) : "r"(addr));
}

// ---------------- shared GEMM inner machinery ------------------------------------
#define AW 136   // bf16 per padded smem row

// One full K=128 pass: acc[2][8][4] += A(smem hi/lo) @ Wtab, j-major mma ordering.
__device__ __forceinline__ void mma_pass(
    uint32_t aHiBase, uint32_t aLoBase, const uint4* __restrict__ Wtab,
    int J0, int lid, int R, float acc[2][8][4]) {
    const int lrow = (lid & 7) + ((lid >> 3) & 1) * 8;
    const int lcol = (lid >> 4) * 8;
#pragma unroll
    for (int katom = 0; katom < 8; katom++) {
        const int k0 = katom * 16;
        uint32_t ahi[2][4], alo[2][4];
#pragma unroll
        for (int m = 0; m < 2; m++) {
            uint32_t off = (uint32_t)((R + m * 16 + lrow) * AW + k0 + lcol) * 2;
            ldmatrix_x4(ahi[m], aHiBase + off);
            ldmatrix_x4(alo[m], aLoBase + off);
        }
#pragma unroll
        for (int grp = 0; grp < 2; grp++) {
            uint4 wf[4];
#pragma unroll
            for (int jj = 0; jj < 4; jj++)
                wf[jj] = __ldg(&Wtab[(((size_t)(J0 + grp * 4 + jj)) * 8 + katom) * 32 + lid]);
            // j-major issue: same-acc reuse distance = 8 mmas
#pragma unroll
            for (int jj = 0; jj < 4; jj++)
                mma_bf16(acc[0][grp * 4 + jj], ahi[0], wf[jj].x, wf[jj].y);
#pragma unroll
            for (int jj = 0; jj < 4; jj++)
                mma_bf16(acc[1][grp * 4 + jj], ahi[1], wf[jj].x, wf[jj].y);
#pragma unroll
            for (int jj = 0; jj < 4; jj++)
                mma_bf16(acc[0][grp * 4 + jj], ahi[0], wf[jj].z, wf[jj].w);
#pragma unroll
            for (int jj = 0; jj < 4; jj++)
                mma_bf16(acc[1][grp * 4 + jj], ahi[1], wf[jj].z, wf[jj].w);
#pragma unroll
            for (int jj = 0; jj < 4; jj++)
                mma_bf16(acc[0][grp * 4 + jj], alo[0], wf[jj].x, wf[jj].y);
#pragma unroll
            for (int jj = 0; jj < 4; jj++)
                mma_bf16(acc[1][grp * 4 + jj], alo[1], wf[jj].x, wf[jj].y);
        }
    }
}

// ---------------- small kernels -------------------------------------------------
__global__ void zero_out_kernel(float* out, int n) {
    int i = blockIdx.x * blockDim.x + threadIdx.x;
    if (i < n) out[i] = 0.0f;
}
__global__ void zero_csr_kernel(int n) {
    int i = blockIdx.x * blockDim.x + threadIdx.x;
    if (i < n) { g_cnt[i] = 0; g_tmp[i] = 0; }
}
__global__ void hist_kernel(const int* __restrict__ ei, int Ee) {
    int e = blockIdx.x * blockDim.x + threadIdx.x;
    if (e >= Ee) return;
    atomicAdd(&g_cnt[__ldg(ei + Ee + e)], 1);
}
__global__ void scan_block_kernel(int n) {
    __shared__ int sh[1024];
    int gid = blockIdx.x * 1024 + threadIdx.x;
    int v = (gid < n) ? g_cnt[gid] : 0;
    sh[threadIdx.x] = v;
    __syncthreads();
    for (int off = 1; off < 1024; off <<= 1) {
        int t = (threadIdx.x >= off) ? sh[threadIdx.x - off] : 0;
        __syncthreads();
        sh[threadIdx.x] += t;
        __syncthreads();
    }
    if (gid < n) g_cnt[gid] = sh[threadIdx.x];
    if (threadIdx.x == 1023) g_bsum[blockIdx.x] = sh[1023];
}
__global__ void scan_bsum_kernel(int nb) {
    if (threadIdx.x == 0) {
        int acc = 0;
        for (int i = 0; i < nb; i++) { int t = g_bsum[i]; g_bsum[i] = acc; acc += t; }
    }
}
__global__ void scan_final_kernel(int n) {
    int gid = blockIdx.x * 1024 + threadIdx.x;
    if (gid < n) g_rowptr[gid + 1] = g_cnt[gid] + g_bsum[blockIdx.x];
    if (gid == 0) g_rowptr[0] = 0;
}
__global__ void fill_csr_kernel(const int* __restrict__ ei, int Ee) {
    int e = blockIdx.x * blockDim.x + threadIdx.x;
    if (e >= Ee) return;
    int src = __ldg(ei + e);
    int dst = __ldg(ei + Ee + e);
    int pos = g_rowptr[dst] + atomicAdd(&g_tmp[dst], 1);
    g_csr_src[pos] = src;
}
// warp per node: agg[n] = (1+eps)*feat[n] + sum_{e in CSR[n]} feat[src_e]
__global__ void gather_kernel(const float* __restrict__ feat,
                              const float* __restrict__ eps, int layer,
                              float* __restrict__ agg, int Nn) {
    int n = (blockIdx.x * blockDim.x + threadIdx.x) >> 5;
    int lane = threadIdx.x & 31;
    if (n >= Nn) return;
    float sc = 1.0f + __ldg(eps + layer);
    float4 self = *(const float4*)(feat + (size_t)n * H + lane * 4);
    float4 acc;
    acc.x = self.x * sc; acc.y = self.y * sc;
    acc.z = self.z * sc; acc.w = self.w * sc;
    int s = g_rowptr[n], e = g_rowptr[n + 1];
    int i = s;
    for (; i + 3 < e; i += 4) {
        int s0 = __ldg(g_csr_src + i);
        int s1 = __ldg(g_csr_src + i + 1);
        int s2 = __ldg(g_csr_src + i + 2);
        int s3 = __ldg(g_csr_src + i + 3);
        float4 v0 = *(const float4*)(feat + (size_t)s0 * H + lane * 4);
        float4 v1 = *(const float4*)(feat + (size_t)s1 * H + lane * 4);
        float4 v2 = *(const float4*)(feat + (size_t)s2 * H + lane * 4);
        float4 v3 = *(const float4*)(feat + (size_t)s3 * H + lane * 4);
        acc.x += (v0.x + v1.x) + (v2.x + v3.x);
        acc.y += (v0.y + v1.y) + (v2.y + v3.y);
        acc.z += (v0.z + v1.z) + (v2.z + v3.z);
        acc.w += (v0.w + v1.w) + (v2.w + v3.w);
    }
    for (; i < e; i++) {
        int s0 = __ldg(g_csr_src + i);
        float4 v0 = *(const float4*)(feat + (size_t)s0 * H + lane * 4);
        acc.x += v0.x; acc.y += v0.y; acc.z += v0.z; acc.w += v0.w;
    }
    *(float4*)(agg + (size_t)n * H + lane * 4) = acc;
}

// Fold BN into weights AND pack bf16 hi/lo mma B-fragments.
__global__ void fold_all_kernel(
    const float* __restrict__ bn_g, const float* __restrict__ bn_b,
    const float* __restrict__ bn_m, const float* __restrict__ bn_v,
    const float* __restrict__ lin_w, const float* __restrict__ lin_b,
    const float* __restrict__ mbn_g, const float* __restrict__ mbn_b,
    const float* __restrict__ mbn_m, const float* __restrict__ mbn_v,
    const float* __restrict__ mlp_w1, const float* __restrict__ mlp_b1,
    const float* __restrict__ mlp_w2, const float* __restrict__ mlp_b2,
    uint4* __restrict__ Wf, float* __restrict__ bo) {
    const int slot = blockIdx.x;       // 0..8
    const int l = slot / 3;
    const int type = slot % 3;
    const int n = threadIdx.x;

    __shared__ float ss[H], st[H];
    float sv = 1.0f, tv = 0.0f;
    if (type == 0) {
        float s = bn_g[l * H + n] * rsqrtf(bn_v[l * H + n] + BN_EPS);
        ss[n] = s;
        st[n] = bn_b[l * H + n] - bn_m[l * H + n] * s;
        __syncthreads();
    } else if (type == 1) {
        sv = mbn_g[l * H + n] * rsqrtf(mbn_v[l * H + n] + BN_EPS);
        tv = mbn_b[l * H + n] - mbn_m[l * H + n] * sv;
    }

    const float* W;
    if (type == 0)      W = lin_w  + (size_t)l * H * H;
    else if (type == 1) W = mlp_w1 + (size_t)l * H * H;
    else                W = mlp_w2 + (size_t)l * H * H;

    float bias_acc;
    if (type == 0) {
        bias_acc = lin_b[l * H + n];
        for (int cc = 0; cc < H; cc++)
            bias_acc += st[cc] * W[cc * H + n];
    } else if (type == 1) {
        bias_acc = mlp_b1[l * H + n] * sv + tv;
    } else {
        bias_acc = mlp_b2[l * H + n];
    }
    bo[slot * H + n] = bias_acc;

    const int J = n >> 3;
    const int g = n & 7;
    for (int katom = 0; katom < 8; katom++) {
#pragma unroll
        for (int tg = 0; tg < 4; tg++) {
            int k0 = katom * 16 + tg * 2;
            float v00, v01, v10, v11;
            if (type == 0) {
                v00 = ss[k0]     * W[(k0)     * H + n];
                v01 = ss[k0 + 1] * W[(k0 + 1) * H + n];
                v10 = ss[k0 + 8] * W[(k0 + 8) * H + n];
                v11 = ss[k0 + 9] * W[(k0 + 9) * H + n];
            } else {
                v00 = W[(k0)     * H + n] * sv;
                v01 = W[(k0 + 1) * H + n] * sv;
                v10 = W[(k0 + 8) * H + n] * sv;
                v11 = W[(k0 + 9) * H + n] * sv;
            }
            float h00 = bf16_rt(v00), h01 = bf16_rt(v01);
            float h10 = bf16_rt(v10), h11 = bf16_rt(v11);
            uint4 out;
            out.x = pack_bf16x2(h00, h01);
            out.y = pack_bf16x2(h10, h11);
            out.z = pack_bf16x2(v00 - h00, v01 - h01);
            out.w = pack_bf16x2(v10 - h10, v11 - h11);
            int lane = g * 4 + tg;
            Wf[(((size_t)slot * 16 + J) * 8 + katom) * 32 + lane] = out;
        }
    }
}

// ---------------- smem layout for GEMM kernels -----------------------------------
static constexpr int SM_AHI   = 0;
static constexpr int SM_ALO   = 128 * AW * 2;            // 34816
static constexpr int SM_BIAS1 = 2 * 128 * AW * 2;        // 69632
static constexpr int SM_BIAS2 = SM_BIAS1 + 512;
static constexpr int SM_RO    = SM_BIAS2 + 512;
static constexpr int SM_TOTAL_G = SM_RO + 512;           // 71168

// ---------------- single GEMM: C = op(A @ W + b) ---------------------------------
template <bool RELU, bool GATH>
__global__ void __launch_bounds__(256, 2)
gemm_bf16(const float* __restrict__ A, const int* __restrict__ gather,
          const uint4* __restrict__ Wf, const float* __restrict__ bias,
          float* __restrict__ C, int M) {
    extern __shared__ char smem[];
    __nv_bfloat16* sAhi = (__nv_bfloat16*)(smem + SM_AHI);
    __nv_bfloat16* sAlo = (__nv_bfloat16*)(smem + SM_ALO);
    float* sBias = (float*)(smem + SM_BIAS1);

    const int tid = threadIdx.x;
    const int wid = tid >> 5, lid = tid & 31;
    const int m0 = blockIdx.x * 128;
    const int J0 = (wid >> 2) * 8;
    const int R = (wid & 3) * 32;

    if (tid < H) sBias[tid] = bias[tid];

#pragma unroll
    for (int i = 0; i < 16; i++) {
        int idx = tid + i * 256;
        int row = idx >> 5;
        int c4  = idx & 31;
        int m = m0 + row;
        float4 v = make_float4(0.f, 0.f, 0.f, 0.f);
        if (m < M) {
            const float* src;
            if (GATH) src = A + (size_t)__ldg(gather + m) * H;
            else      src = A + (size_t)m * H;
            v = *(const float4*)(src + c4 * 4);
        }
        float hx = bf16_rt(v.x), hy = bf16_rt(v.y);
        float hz = bf16_rt(v.z), hw = bf16_rt(v.w);
        uint2 hpack, lpack;
        hpack.x = pack_bf16x2(hx, hy);
        hpack.y = pack_bf16x2(hz, hw);
        lpack.x = pack_bf16x2(v.x - hx, v.y - hy);
        lpack.y = pack_bf16x2(v.z - hz, v.w - hw);
        *(uint2*)&sAhi[row * AW + c4 * 4] = hpack;
        *(uint2*)&sAlo[row * AW + c4 * 4] = lpack;
    }
    __syncthreads();

    float acc[2][8][4];
#pragma unroll
    for (int m = 0; m < 2; m++)
#pragma unroll
        for (int j = 0; j < 8; j++)
#pragma unroll
            for (int r = 0; r < 4; r++) acc[m][j][r] = 0.0f;

    mma_pass(smem_addr_u32(sAhi), smem_addr_u32(sAlo), Wf, J0, lid, R, acc);

    const int r0 = m0 + R;
    const int cb = (wid >> 2) * 64;
    const int g = lid >> 2, tg = lid & 3;
#pragma unroll
    for (int m = 0; m < 2; m++) {
#pragma unroll
        for (int rh = 0; rh < 2; rh++) {
            int row = r0 + m * 16 + rh * 8 + g;
            if (row < M) {
#pragma unroll
                for (int j = 0; j < 8; j++) {
                    int c = cb + j * 8 + tg * 2;
                    float2 o;
                    o.x = acc[m][j][rh * 2 + 0] + sBias[c];
                    o.y = acc[m][j][rh * 2 + 1] + sBias[c + 1];
                    if (RELU) { o.x = fmaxf(o.x, 0.f); o.y = fmaxf(o.y, 0.f); }
                    *(float2*)(C + (size_t)row * H + c) = o;
                }
            }
        }
    }
}

// ---------------- fused dual GEMM: h = (relu(A@W1+b1)) @ W2 + b2 (+readout) ------
template <bool RDOUT>
__global__ void __launch_bounds__(256, 2)
gemm_bf16_dual(const float* __restrict__ A,
               const uint4* __restrict__ Wf1, const float* __restrict__ b1,
               const uint4* __restrict__ Wf2, const float* __restrict__ b2,
               float* __restrict__ Cout,
               const int* __restrict__ batch, const float* __restrict__ ro_w,
               const float* __restrict__ ro_b, float* __restrict__ gout, int M) {
    extern __shared__ char smem[];
    __nv_bfloat16* sAhi = (__nv_bfloat16*)(smem + SM_AHI);
    __nv_bfloat16* sAlo = (__nv_bfloat16*)(smem + SM_ALO);
    float* sBias1 = (float*)(smem + SM_BIAS1);
    float* sBias2 = (float*)(smem + SM_BIAS2);
    float* sRo    = (float*)(smem + SM_RO);

    const int tid = threadIdx.x;
    const int wid = tid >> 5, lid = tid & 31;
    const int m0 = blockIdx.x * 128;
    const int J0 = (wid >> 2) * 8;
    const int R = (wid & 3) * 32;
    const uint32_t aHiBase = smem_addr_u32(sAhi);
    const uint32_t aLoBase = smem_addr_u32(sAlo);

    if (tid < H) {
        sBias1[tid] = b1[tid];
        sBias2[tid] = b2[tid];
        if (RDOUT) sRo[tid] = ro_w[tid];
    }

    // ---- stage A (agg) ----
#pragma unroll
    for (int i = 0; i < 16; i++) {
        int idx = tid + i * 256;
        int row = idx >> 5;
        int c4  = idx & 31;
        int m = m0 + row;
        float4 v = make_float4(0.f, 0.f, 0.f, 0.f);
        if (m < M) v = *(const float4*)(A + (size_t)m * H + c4 * 4);
        float hx = bf16_rt(v.x), hy = bf16_rt(v.y);
        float hz = bf16_rt(v.z), hw = bf16_rt(v.w);
        uint2 hpack, lpack;
        hpack.x = pack_bf16x2(hx, hy);
        hpack.y = pack_bf16x2(hz, hw);
        lpack.x = pack_bf16x2(v.x - hx, v.y - hy);
        lpack.y = pack_bf16x2(v.z - hz, v.w - hw);
        *(uint2*)&sAhi[row * AW + c4 * 4] = hpack;
        *(uint2*)&sAlo[row * AW + c4 * 4] = lpack;
    }
    __syncthreads();

    float acc[2][8][4];
#pragma unroll
    for (int m = 0; m < 2; m++)
#pragma unroll
        for (int j = 0; j < 8; j++)
#pragma unroll
            for (int r = 0; r < 4; r++) acc[m][j][r] = 0.0f;

    // ---- phase 1: z = relu(A @ W1 + b1) ----
    mma_pass(aHiBase, aLoBase, Wf1, J0, lid, R, acc);

    const int cb = (wid >> 2) * 64;
    const int g = lid >> 2, tg = lid & 3;

    __syncthreads();   // all warps done reading A from smem
    // write z into the same smem buffers (bank-conflict-free: (4g+tg)%32 distinct)
#pragma unroll
    for (int m = 0; m < 2; m++) {
#pragma unroll
        for (int rh = 0; rh < 2; rh++) {
            int row = R + m * 16 + rh * 8 + g;   // local row 0..127
#pragma unroll
            for (int j = 0; j < 8; j++) {
                int c = cb + j * 8 + tg * 2;
                float zx = fmaxf(acc[m][j][rh * 2 + 0] + sBias1[c], 0.f);
                float zy = fmaxf(acc[m][j][rh * 2 + 1] + sBias1[c + 1], 0.f);
                float hx = bf16_rt(zx), hy = bf16_rt(zy);
                *(uint32_t*)&sAhi[row * AW + c] = pack_bf16x2(hx, hy);
                *(uint32_t*)&sAlo[row * AW + c] = pack_bf16x2(zx - hx, zy - hy);
            }
        }
    }
    __syncthreads();

#pragma unroll
    for (int m = 0; m < 2; m++)
#pragma unroll
        for (int j = 0; j < 8; j++)
#pragma unroll
            for (int r = 0; r < 4; r++) acc[m][j][r] = 0.0f;

    // ---- phase 2: h = z @ W2 + b2 ----
    mma_pass(aHiBase, aLoBase, Wf2, J0, lid, R, acc);

    const int r0 = m0 + R;
    float dots[4] = {0.f, 0.f, 0.f, 0.f};
#pragma unroll
    for (int m = 0; m < 2; m++) {
#pragma unroll
        for (int rh = 0; rh < 2; rh++) {
            int row = r0 + m * 16 + rh * 8 + g;
            if (row < M) {
                float dv = 0.f;
#pragma unroll
                for (int j = 0; j < 8; j++) {
                    int c = cb + j * 8 + tg * 2;
                    float2 o;
                    o.x = acc[m][j][rh * 2 + 0] + sBias2[c];
                    o.y = acc[m][j][rh * 2 + 1] + sBias2[c + 1];
                    *(float2*)(Cout + (size_t)row * H + c) = o;
                    if (RDOUT) dv += o.x * sRo[c] + o.y * sRo[c + 1];
                }
                if (RDOUT) dots[m * 2 + rh] = dv;
            }
        }
    }
    if (RDOUT) {
#pragma unroll
        for (int s = 0; s < 4; s++) {
            float v = dots[s];
            v += __shfl_xor_sync(0xffffffff, v, 1);
            v += __shfl_xor_sync(0xffffffff, v, 2);
            int row = r0 + (s >> 1) * 16 + (s & 1) * 8 + g;
            if (tg == 0 && row < M) {
                if (cb == 0) v += __ldg(ro_b);
                atomicAdd(gout + __ldg(batch + row), v);
            }
        }
    }
}

// ---------------- launcher ------------------------------------------------------
extern "C" void kernel_launch(void* const* d_in, const int* in_sizes, int n_in,
                              void* d_out, int out_size) {
    const int*   x      = (const int*)d_in[0];
    const int*   ei     = (const int*)d_in[1];
    const int*   batch  = (const int*)d_in[2];
    const float* table  = (const float*)d_in[3];
    const float* bn_g   = (const float*)d_in[4];
    const float* bn_b   = (const float*)d_in[5];
    const float* bn_m   = (const float*)d_in[6];
    const float* bn_v   = (const float*)d_in[7];
    const float* lin_w  = (const float*)d_in[8];
    const float* lin_b  = (const float*)d_in[9];
    const float* eps    = (const float*)d_in[10];
    const float* mlp_w1 = (const float*)d_in[11];
    const float* mlp_b1 = (const float*)d_in[12];
    const float* mbn_g  = (const float*)d_in[13];
    const float* mbn_b  = (const float*)d_in[14];
    const float* mbn_m  = (const float*)d_in[15];
    const float* mbn_v  = (const float*)d_in[16];
    const float* mlp_w2 = (const float*)d_in[17];
    const float* mlp_b2 = (const float*)d_in[18];
    const float* ro_w   = (const float*)d_in[19];
    const float* ro_b   = (const float*)d_in[20];

    const int Nn = in_sizes[0];
    const int Ee = in_sizes[1] / 2;
    const int Gg = out_size;

    float *h, *t, *agg, *bf;
    uint4* Wf;
    cudaGetSymbolAddress((void**)&h,   g_h);
    cudaGetSymbolAddress((void**)&t,   g_t);
    cudaGetSymbolAddress((void**)&agg, g_agg);
    cudaGetSymbolAddress((void**)&Wf,  g_Wfrag);
    cudaGetSymbolAddress((void**)&bf,  g_bf);

    cudaFuncSetAttribute(gemm_bf16<true, true >, cudaFuncAttributeMaxDynamicSharedMemorySize, SM_TOTAL_G);
    cudaFuncSetAttribute(gemm_bf16<true, false>, cudaFuncAttributeMaxDynamicSharedMemorySize, SM_TOTAL_G);
    cudaFuncSetAttribute(gemm_bf16_dual<true >, cudaFuncAttributeMaxDynamicSharedMemorySize, SM_TOTAL_G);
    cudaFuncSetAttribute(gemm_bf16_dual<false>, cudaFuncAttributeMaxDynamicSharedMemorySize, SM_TOTAL_G);

    const int gemm_grid = (Nn + 127) / 128;
    const int edge_grid = (Ee + 255) / 256;
    const int node_grid = (Nn + 1023) / 1024;
    const int warp_grid = ((Nn * 32) + 255) / 256;

    // Launch order keeps #4 = layer-0 GEMM for comparable ncu captures.
    zero_out_kernel<<<(Gg + 255) / 256, 256>>>((float*)d_out, Gg);            // 1
    zero_csr_kernel<<<(Nn + 255) / 256, 256>>>(Nn);                           // 2
    fold_all_kernel<<<9, H>>>(bn_g, bn_b, bn_m, bn_v, lin_w, lin_b,           // 3
                              mbn_g, mbn_b, mbn_m, mbn_v, mlp_w1, mlp_b1,
                              mlp_w2, mlp_b2, Wf, bf);
    // layer-0: t := relu(BN(embed[x]) @ lin + b)
    gemm_bf16<true, true><<<gemm_grid, 256, SM_TOTAL_G>>>(                    // 4
        table, x, Wf, bf, t, Nn);
    // CSR build
    hist_kernel<<<edge_grid, 256>>>(ei, Ee);                                  // 5
    scan_block_kernel<<<node_grid, 1024>>>(Nn);
    scan_bsum_kernel<<<1, 32>>>(node_grid);
    scan_final_kernel<<<node_grid, 1024>>>(Nn);
    fill_csr_kernel<<<edge_grid, 256>>>(ei, Ee);

    for (int l = 0; l < 3; l++) {
        const uint4* W1 = Wf + (size_t)(3 * l + 0) * 16 * 8 * 32;
        const uint4* W2 = Wf + (size_t)(3 * l + 1) * 16 * 8 * 32;
        const uint4* W3 = Wf + (size_t)(3 * l + 2) * 16 * 8 * 32;
        const float* b1 = bf + (3 * l + 0) * H;
        const float* b2 = bf + (3 * l + 1) * H;
        const float* b3 = bf + (3 * l + 2) * H;

        if (l > 0)
            gemm_bf16<true, false><<<gemm_grid, 256, SM_TOTAL_G>>>(
                h, nullptr, W1, b1, t, Nn);

        // agg[n] := (1+eps)*t[n] + sum over CSR neighbors of t
        gather_kernel<<<warp_grid, 256>>>(t, eps, l, agg, Nn);

        // fused: h := relu(BN(agg@mlp_w1+b1)) @ mlp_w2 + b2  (+readout last layer)
        if (l == 2)
            gemm_bf16_dual<true><<<gemm_grid, 256, SM_TOTAL_G>>>(
                agg, W2, b2, W3, b3, h, batch, ro_w, ro_b, (float*)d_out, Nn);
        else
            gemm_bf16_dual<false><<<gemm_grid, 256, SM_TOTAL_G>>>(
                agg, W2, b2, W3, b3, h, nullptr, nullptr, nullptr, nullptr, Nn);
    }
}

// round 9
// speedup vs baseline: 3.1645x; 1.0912x over previous
#include <cuda_runtime.h>
#include <cuda_bf16.h>
#include <cstdint>

#define H 128
#define MAXN 50000
#define MAXE 800000
#define BN_EPS 1e-5f

// ---------------- device scratch ---------------------------------------------
__device__ float g_t[MAXN * H];
__device__ float g_agg[MAXN * H];
// Fragment slots: 0:G1(SL0) 1:Bz0 2:Cc0 3:Bz1 4:Cc1 5:Bz2
__device__ uint4 g_Wfrag[6 * 16 * 8 * 32];
__device__ float g_bf[6 * H];
// fp32 fold scratch
__device__ float g_scr[6 * H * H];
__device__ float g_SL[2 * H * H];     // SL_1, SL_2 (diag(s)*lin for layers 1,2)
__device__ float g_bfold[2 * H];      // bfold_1, bfold_2
__device__ float g_rov[H];            // W2_2 @ ro_w
__device__ float g_roc[1];            // b2_2 . ro_w + ro_b
// CSR scratch
__device__ int g_cnt[MAXN];
__device__ int g_tmp[MAXN];
__device__ int g_rowptr[MAXN + 1];
__device__ int g_csr_src[MAXE];
__device__ int g_bsum[64];

// ---------------- helpers -------------------------------------------------------
__device__ __forceinline__ uint32_t smem_addr_u32(const void* p) {
    uint32_t a;
    asm("{ .reg .u64 t; cvta.to.shared.u64 t, %1; cvt.u32.u64 %0, t; }" : "=r"(a) : "l"(p));
    return a;
}
__device__ __forceinline__ uint32_t pack_bf16x2(float a, float b) {
    uint32_t ua = (uint32_t)__bfloat16_as_ushort(__float2bfloat16_rn(a));
    uint32_t ub = (uint32_t)__bfloat16_as_ushort(__float2bfloat16_rn(b));
    return ua | (ub << 16);
}
__device__ __forceinline__ float bf16_rt(float x) {
    return __bfloat162float(__float2bfloat16_rn(x));
}
__device__ __forceinline__ void mma_bf16(float* d, const uint32_t* a,
                                         uint32_t b0, uint32_t b1) {
    asm volatile(
        "mma.sync.aligned.m16n8k16.row.col.f32.bf16.bf16.f32 "
        "{%0,%1,%2,%3}, {%4,%5,%6,%7}, {%8,%9}, {%0,%1,%2,%3};"
        : "+f"(d[0]), "+f"(d[1]), "+f"(d[2]), "+f"(d[3])
        : "r"(a[0]), "r"(a[1]), "r"(a[2]), "r"(a[3]), "r"(b0), "r"(b1));
}
__device__ __forceinline__ void ldmatrix_x4(uint32_t* r, uint32_t addr) {
    asm volatile("ldmatrix.sync.aligned.m8n8.x4.shared.b16 {%0,%1,%2,%3}, [%4];"
                 : "=r"(r[0]), "=r"(r[1]), "=r"(r[2]), "=r"(r[3]) : "r"(addr));
}

// ---------------- shared GEMM inner machinery ------------------------------------
#define AW 136   // bf16 per padded smem row

__device__ __forceinline__ void mma_pass(
    uint32_t aHiBase, uint32_t aLoBase, const uint4* __restrict__ Wtab,
    int J0, int lid, int R, float acc[2][8][4]) {
    const int lrow = (lid & 7) + ((lid >> 3) & 1) * 8;
    const int lcol = (lid >> 4) * 8;
#pragma unroll
    for (int katom = 0; katom < 8; katom++) {
        const int k0 = katom * 16;
        uint32_t ahi[2][4], alo[2][4];
#pragma unroll
        for (int m = 0; m < 2; m++) {
            uint32_t off = (uint32_t)((R + m * 16 + lrow) * AW + k0 + lcol) * 2;
            ldmatrix_x4(ahi[m], aHiBase + off);
            ldmatrix_x4(alo[m], aLoBase + off);
        }
#pragma unroll
        for (int grp = 0; grp < 2; grp++) {
            uint4 wf[4];
#pragma unroll
            for (int jj = 0; jj < 4; jj++)
                wf[jj] = __ldg(&Wtab[(((size_t)(J0 + grp * 4 + jj)) * 8 + katom) * 32 + lid]);
#pragma unroll
            for (int jj = 0; jj < 4; jj++)
                mma_bf16(acc[0][grp * 4 + jj], ahi[0], wf[jj].x, wf[jj].y);
#pragma unroll
            for (int jj = 0; jj < 4; jj++)
                mma_bf16(acc[1][grp * 4 + jj], ahi[1], wf[jj].x, wf[jj].y);
#pragma unroll
            for (int jj = 0; jj < 4; jj++)
                mma_bf16(acc[0][grp * 4 + jj], ahi[0], wf[jj].z, wf[jj].w);
#pragma unroll
            for (int jj = 0; jj < 4; jj++)
                mma_bf16(acc[1][grp * 4 + jj], ahi[1], wf[jj].z, wf[jj].w);
#pragma unroll
            for (int jj = 0; jj < 4; jj++)
                mma_bf16(acc[0][grp * 4 + jj], alo[0], wf[jj].x, wf[jj].y);
#pragma unroll
            for (int jj = 0; jj < 4; jj++)
                mma_bf16(acc[1][grp * 4 + jj], alo[1], wf[jj].x, wf[jj].y);
        }
    }
}

// Stage 128x128 fp32 rows (from src base, optional gather) as bf16 hi/lo in smem.
template <bool GATH>
__device__ __forceinline__ void stage_tile(
    const float* __restrict__ A, const int* __restrict__ gather,
    __nv_bfloat16* sAhi, __nv_bfloat16* sAlo, int m0, int M, int tid) {
#pragma unroll
    for (int i = 0; i < 16; i++) {
        int idx = tid + i * 256;
        int row = idx >> 5;
        int c4  = idx & 31;
        int m = m0 + row;
        float4 v = make_float4(0.f, 0.f, 0.f, 0.f);
        if (m < M) {
            const float* src;
            if (GATH) src = A + (size_t)__ldg(gather + m) * H;
            else      src = A + (size_t)m * H;
            v = *(const float4*)(src + c4 * 4);
        }
        float hx = bf16_rt(v.x), hy = bf16_rt(v.y);
        float hz = bf16_rt(v.z), hw = bf16_rt(v.w);
        uint2 hpack, lpack;
        hpack.x = pack_bf16x2(hx, hy);
        hpack.y = pack_bf16x2(hz, hw);
        lpack.x = pack_bf16x2(v.x - hx, v.y - hy);
        lpack.y = pack_bf16x2(v.z - hz, v.w - hw);
        *(uint2*)&sAhi[row * AW + c4 * 4] = hpack;
        *(uint2*)&sAlo[row * AW + c4 * 4] = lpack;
    }
}

// ---------------- small kernels -------------------------------------------------
__global__ void zero_out_kernel(float* out, int n) {
    int i = blockIdx.x * blockDim.x + threadIdx.x;
    if (i < n) out[i] = 0.0f;
}
__global__ void zero_csr_kernel(int n) {
    int i = blockIdx.x * blockDim.x + threadIdx.x;
    if (i < n) { g_cnt[i] = 0; g_tmp[i] = 0; }
}
__global__ void hist_kernel(const int* __restrict__ ei, int Ee) {
    int e = blockIdx.x * blockDim.x + threadIdx.x;
    if (e >= Ee) return;
    atomicAdd(&g_cnt[__ldg(ei + Ee + e)], 1);
}
__global__ void scan_block_kernel(int n) {
    __shared__ int sh[1024];
    int gid = blockIdx.x * 1024 + threadIdx.x;
    int v = (gid < n) ? g_cnt[gid] : 0;
    sh[threadIdx.x] = v;
    __syncthreads();
    for (int off = 1; off < 1024; off <<= 1) {
        int t = (threadIdx.x >= off) ? sh[threadIdx.x - off] : 0;
        __syncthreads();
        sh[threadIdx.x] += t;
        __syncthreads();
    }
    if (gid < n) g_cnt[gid] = sh[threadIdx.x];
    if (threadIdx.x == 1023) g_bsum[blockIdx.x] = sh[1023];
}
__global__ void scan_bsum_kernel(int nb) {
    if (threadIdx.x == 0) {
        int acc = 0;
        for (int i = 0; i < nb; i++) { int t = g_bsum[i]; g_bsum[i] = acc; acc += t; }
    }
}
__global__ void scan_final_kernel(int n) {
    int gid = blockIdx.x * 1024 + threadIdx.x;
    if (gid < n) g_rowptr[gid + 1] = g_cnt[gid] + g_bsum[blockIdx.x];
    if (gid == 0) g_rowptr[0] = 0;
}
__global__ void fill_csr_kernel(const int* __restrict__ ei, int Ee) {
    int e = blockIdx.x * blockDim.x + threadIdx.x;
    if (e >= Ee) return;
    int src = __ldg(ei + e);
    int dst = __ldg(ei + Ee + e);
    int pos = g_rowptr[dst] + atomicAdd(&g_tmp[dst], 1);
    g_csr_src[pos] = src;
}
__global__ void gather_kernel(const float* __restrict__ feat,
                              const float* __restrict__ eps, int layer,
                              float* __restrict__ agg, int Nn) {
    int n = (blockIdx.x * blockDim.x + threadIdx.x) >> 5;
    int lane = threadIdx.x & 31;
    if (n >= Nn) return;
    float sc = 1.0f + __ldg(eps + layer);
    float4 self = *(const float4*)(feat + (size_t)n * H + lane * 4);
    float4 acc;
    acc.x = self.x * sc; acc.y = self.y * sc;
    acc.z = self.z * sc; acc.w = self.w * sc;
    int s = g_rowptr[n], e = g_rowptr[n + 1];
    int i = s;
    for (; i + 3 < e; i += 4) {
        int s0 = __ldg(g_csr_src + i);
        int s1 = __ldg(g_csr_src + i + 1);
        int s2 = __ldg(g_csr_src + i + 2);
        int s3 = __ldg(g_csr_src + i + 3);
        float4 v0 = *(const float4*)(feat + (size_t)s0 * H + lane * 4);
        float4 v1 = *(const float4*)(feat + (size_t)s1 * H + lane * 4);
        float4 v2 = *(const float4*)(feat + (size_t)s2 * H + lane * 4);
        float4 v3 = *(const float4*)(feat + (size_t)s3 * H + lane * 4);
        acc.x += (v0.x + v1.x) + (v2.x + v3.x);
        acc.y += (v0.y + v1.y) + (v2.y + v3.y);
        acc.z += (v0.z + v1.z) + (v2.z + v3.z);
        acc.w += (v0.w + v1.w) + (v2.w + v3.w);
    }
    for (; i < e; i++) {
        int s0 = __ldg(g_csr_src + i);
        float4 v0 = *(const float4*)(feat + (size_t)s0 * H + lane * 4);
        acc.x += v0.x; acc.y += v0.y; acc.z += v0.z; acc.w += v0.w;
    }
    *(float4*)(agg + (size_t)n * H + lane * 4) = acc;
}

// ---------------- fold stage 1: BN-scaled matrices into fp32 scratch -------------
__global__ void fold_scale_kernel(
    const float* __restrict__ bn_g, const float* __restrict__ bn_b,
    const float* __restrict__ bn_m, const float* __restrict__ bn_v,
    const float* __restrict__ lin_w, const float* __restrict__ lin_b,
    const float* __restrict__ mbn_g, const float* __restrict__ mbn_b,
    const float* __restrict__ mbn_m, const float* __restrict__ mbn_v,
    const float* __restrict__ mlp_w1, const float* __restrict__ mlp_b1) {
    const int b = blockIdx.x;       // 0..5
    const int n = threadIdx.x;
    if (b < 3) {
        // SL_l = diag(s_l)*lin_l ; bfold_l = lin_b + st@lin
        int l = b;
        __shared__ float ss[H], st[H];
        float s = bn_g[l * H + n] * rsqrtf(bn_v[l * H + n] + BN_EPS);
        ss[n] = s;
        st[n] = bn_b[l * H + n] - bn_m[l * H + n] * s;
        __syncthreads();
        const float* W = lin_w + (size_t)l * H * H;
        float* dst = (l == 0) ? g_scr : (g_SL + (size_t)(l - 1) * H * H);
        float bias = lin_b[l * H + n];
        for (int c = 0; c < H; c++) {
            float w = W[c * H + n];
            dst[c * H + n] = ss[c] * w;
            bias += st[c] * w;
        }
        if (l == 0) g_bf[n] = bias;
        else        g_bfold[(l - 1) * H + n] = bias;
    } else {
        // Bz_l = mlp_w1_l * diag(sv) ; bz
        int l = b - 3;
        float sv = mbn_g[l * H + n] * rsqrtf(mbn_v[l * H + n] + BN_EPS);
        float tv = mbn_b[l * H + n] - mbn_m[l * H + n] * sv;
        const float* W = mlp_w1 + (size_t)l * H * H;
        float* dst = g_scr + (size_t)(1 + 2 * l) * H * H;
        for (int k = 0; k < H; k++)
            dst[k * H + n] = W[k * H + n] * sv;
        g_bf[(1 + 2 * l) * H + n] = mlp_b1[l * H + n] * sv + tv;
    }
}

// ---------------- fold stage 2: Cc_l = W2_l @ SL_{l+1}; readout fold --------------
__global__ void fold_mm_kernel(
    const float* __restrict__ mlp_w2, const float* __restrict__ mlp_b2,
    const float* __restrict__ ro_w, const float* __restrict__ ro_b) {
    const int b = blockIdx.x;       // 0..8
    if (b == 8) {
        __shared__ float ro[H];
        int t = threadIdx.x;
        if (t < H) ro[t] = ro_w[t];
        __syncthreads();
        if (t < H) {
            const float* W2 = mlp_w2 + (size_t)2 * H * H;
            float acc = 0.f;
            for (int j = 0; j < H; j++) acc += W2[t * H + j] * ro[j];
            g_rov[t] = acc;
        }
        if (t == 0) {
            const float* b2 = mlp_b2 + 2 * H;
            float acc = ro_b[0];
            for (int j = 0; j < H; j++) acc += b2[j] * ro[j];
            g_roc[0] = acc;
        }
        return;
    }
    const int l  = b >> 2;          // 0 or 1
    const int m0 = (b & 3) * 32;
    const float* W2 = mlp_w2 + (size_t)l * H * H;
    const float* SL = g_SL + (size_t)l * H * H;
    float* C = g_scr + (size_t)(2 + 2 * l) * H * H;

    __shared__ float sS[32][128];
    const int tm = threadIdx.x >> 4;      // 0..15
    const int tn = threadIdx.x & 15;      // 0..15
    float acc[2][8];
#pragma unroll
    for (int r = 0; r < 2; r++)
#pragma unroll
        for (int j = 0; j < 8; j++) acc[r][j] = 0.f;

    for (int kc = 0; kc < H; kc += 32) {
        for (int i = threadIdx.x; i < 32 * 128; i += 256)
            sS[i >> 7][i & 127] = SL[(size_t)(kc + (i >> 7)) * H + (i & 127)];
        __syncthreads();
        for (int kk = 0; kk < 32; kk++) {
            int k = kc + kk;
            float a0 = W2[(m0 + tm * 2)     * H + k];
            float a1 = W2[(m0 + tm * 2 + 1) * H + k];
#pragma unroll
            for (int j = 0; j < 8; j++) {
                float sv = sS[kk][tn * 8 + j];
                acc[0][j] += a0 * sv;
                acc[1][j] += a1 * sv;
            }
        }
        __syncthreads();
    }
#pragma unroll
    for (int r = 0; r < 2; r++)
#pragma unroll
        for (int j = 0; j < 8; j++)
            C[(size_t)(m0 + tm * 2 + r) * H + tn * 8 + j] = acc[r][j];

    // combined bias: bc[n] = b2 @ SL[:,n] + bfold_{l+1}[n]   (one block per l)
    if ((b & 3) == 0) {
        __syncthreads();
        int n = threadIdx.x;
        if (n < H) {
            const float* b2 = mlp_b2 + l * H;
            float a = g_bfold[l * H + n];
            for (int k = 0; k < H; k++) a += b2[k] * SL[(size_t)k * H + n];
            g_bf[(2 + 2 * l) * H + n] = a;
        }
    }
}

// ---------------- fold stage 3: pack fp32 scratch -> bf16 hi/lo fragments --------
__global__ void pack_kernel() {
    const int slot = blockIdx.x;    // 0..5
    const int n = threadIdx.x;
    const float* W = g_scr + (size_t)slot * H * H;
    const int J = n >> 3;
    const int g = n & 7;
    for (int katom = 0; katom < 8; katom++) {
#pragma unroll
        for (int tg = 0; tg < 4; tg++) {
            int k0 = katom * 16 + tg * 2;
            float v00 = W[(k0)     * H + n];
            float v01 = W[(k0 + 1) * H + n];
            float v10 = W[(k0 + 8) * H + n];
            float v11 = W[(k0 + 9) * H + n];
            float h00 = bf16_rt(v00), h01 = bf16_rt(v01);
            float h10 = bf16_rt(v10), h11 = bf16_rt(v11);
            uint4 out;
            out.x = pack_bf16x2(h00, h01);
            out.y = pack_bf16x2(h10, h11);
            out.z = pack_bf16x2(v00 - h00, v01 - h01);
            out.w = pack_bf16x2(v10 - h10, v11 - h11);
            int lane = g * 4 + tg;
            g_Wfrag[(((size_t)slot * 16 + J) * 8 + katom) * 32 + lane] = out;
        }
    }
}

// ---------------- smem layout for GEMM kernels -----------------------------------
static constexpr int SM_AHI   = 0;
static constexpr int SM_ALO   = 128 * AW * 2;
static constexpr int SM_BIAS1 = 2 * 128 * AW * 2;
static constexpr int SM_BIAS2 = SM_BIAS1 + 512;
static constexpr int SM_RO    = SM_BIAS2 + 512;
static constexpr int SM_TOTAL_G = SM_RO + 512;

// ---------------- G1: t = relu(embed[x] @ SL0 + bfold0) --------------------------
__global__ void __launch_bounds__(256, 2)
gemm_embed(const float* __restrict__ table, const int* __restrict__ xidx,
           const uint4* __restrict__ Wf, const float* __restrict__ bias,
           float* __restrict__ C, int M) {
    extern __shared__ char smem[];
    __nv_bfloat16* sAhi = (__nv_bfloat16*)(smem + SM_AHI);
    __nv_bfloat16* sAlo = (__nv_bfloat16*)(smem + SM_ALO);
    float* sBias = (float*)(smem + SM_BIAS1);

    const int tid = threadIdx.x;
    const int wid = tid >> 5, lid = tid & 31;
    const int m0 = blockIdx.x * 128;
    const int J0 = (wid >> 2) * 8;
    const int R = (wid & 3) * 32;

    if (tid < H) sBias[tid] = bias[tid];
    stage_tile<true>(table, xidx, sAhi, sAlo, m0, M, tid);
    __syncthreads();

    float acc[2][8][4];
#pragma unroll
    for (int m = 0; m < 2; m++)
#pragma unroll
        for (int j = 0; j < 8; j++)
#pragma unroll
            for (int r = 0; r < 4; r++) acc[m][j][r] = 0.0f;

    mma_pass(smem_addr_u32(sAhi), smem_addr_u32(sAlo), Wf, J0, lid, R, acc);

    const int r0 = m0 + R;
    const int cb = (wid >> 2) * 64;
    const int g = lid >> 2, tg = lid & 3;
#pragma unroll
    for (int m = 0; m < 2; m++)
#pragma unroll
        for (int rh = 0; rh < 2; rh++) {
            int row = r0 + m * 16 + rh * 8 + g;
            if (row < M) {
#pragma unroll
                for (int j = 0; j < 8; j++) {
                    int c = cb + j * 8 + tg * 2;
                    float2 o;
                    o.x = fmaxf(acc[m][j][rh * 2 + 0] + sBias[c], 0.f);
                    o.y = fmaxf(acc[m][j][rh * 2 + 1] + sBias[c + 1], 0.f);
                    *(float2*)(C + (size_t)row * H + c) = o;
                }
            }
        }
}

// ---------------- dual: t' = relu( relu(agg@Bz+bz) @ Cc + bc ) --------------------
__global__ void __launch_bounds__(256, 2)
gemm_dual(const float* __restrict__ A,
          const uint4* __restrict__ Wf1, const float* __restrict__ b1,
          const uint4* __restrict__ Wf2, const float* __restrict__ b2,
          float* __restrict__ Cout, int M) {
    extern __shared__ char smem[];
    __nv_bfloat16* sAhi = (__nv_bfloat16*)(smem + SM_AHI);
    __nv_bfloat16* sAlo = (__nv_bfloat16*)(smem + SM_ALO);
    float* sBias1 = (float*)(smem + SM_BIAS1);
    float* sBias2 = (float*)(smem + SM_BIAS2);

    const int tid = threadIdx.x;
    const int wid = tid >> 5, lid = tid & 31;
    const int m0 = blockIdx.x * 128;
    const int J0 = (wid >> 2) * 8;
    const int R = (wid & 3) * 32;
    const uint32_t aHiBase = smem_addr_u32(sAhi);
    const uint32_t aLoBase = smem_addr_u32(sAlo);

    if (tid < H) {
        sBias1[tid] = b1[tid];
        sBias2[tid] = b2[tid];
    }
    stage_tile<false>(A, nullptr, sAhi, sAlo, m0, M, tid);
    __syncthreads();

    float acc[2][8][4];
#pragma unroll
    for (int m = 0; m < 2; m++)
#pragma unroll
        for (int j = 0; j < 8; j++)
#pragma unroll
            for (int r = 0; r < 4; r++) acc[m][j][r] = 0.0f;

    mma_pass(aHiBase, aLoBase, Wf1, J0, lid, R, acc);

    const int cb = (wid >> 2) * 64;
    const int g = lid >> 2, tg = lid & 3;

    __syncthreads();
    // z = relu(acc + b1) -> smem (bf16 hi/lo)
#pragma unroll
    for (int m = 0; m < 2; m++)
#pragma unroll
        for (int rh = 0; rh < 2; rh++) {
            int row = R + m * 16 + rh * 8 + g;
#pragma unroll
            for (int j = 0; j < 8; j++) {
                int c = cb + j * 8 + tg * 2;
                float zx = fmaxf(acc[m][j][rh * 2 + 0] + sBias1[c], 0.f);
                float zy = fmaxf(acc[m][j][rh * 2 + 1] + sBias1[c + 1], 0.f);
                float hx = bf16_rt(zx), hy = bf16_rt(zy);
                *(uint32_t*)&sAhi[row * AW + c] = pack_bf16x2(hx, hy);
                *(uint32_t*)&sAlo[row * AW + c] = pack_bf16x2(zx - hx, zy - hy);
            }
        }
    __syncthreads();

#pragma unroll
    for (int m = 0; m < 2; m++)
#pragma unroll
        for (int j = 0; j < 8; j++)
#pragma unroll
            for (int r = 0; r < 4; r++) acc[m][j][r] = 0.0f;

    mma_pass(aHiBase, aLoBase, Wf2, J0, lid, R, acc);

    const int r0 = m0 + R;
#pragma unroll
    for (int m = 0; m < 2; m++)
#pragma unroll
        for (int rh = 0; rh < 2; rh++) {
            int row = r0 + m * 16 + rh * 8 + g;
            if (row < M) {
#pragma unroll
                for (int j = 0; j < 8; j++) {
                    int c = cb + j * 8 + tg * 2;
                    float2 o;
                    o.x = fmaxf(acc[m][j][rh * 2 + 0] + sBias2[c], 0.f);
                    o.y = fmaxf(acc[m][j][rh * 2 + 1] + sBias2[c + 1], 0.f);
                    *(float2*)(Cout + (size_t)row * H + c) = o;
                }
            }
        }
}

// ---------------- layer-2: z = relu(agg@Bz2+bz2); out += z.v + c -----------------
__global__ void __launch_bounds__(256, 2)
gemm_ro(const float* __restrict__ A,
        const uint4* __restrict__ Wf, const float* __restrict__ bias,
        const int* __restrict__ batch, float* __restrict__ gout, int M) {
    extern __shared__ char smem[];
    __nv_bfloat16* sAhi = (__nv_bfloat16*)(smem + SM_AHI);
    __nv_bfloat16* sAlo = (__nv_bfloat16*)(smem + SM_ALO);
    float* sBias = (float*)(smem + SM_BIAS1);
    float* sRo   = (float*)(smem + SM_RO);

    const int tid = threadIdx.x;
    const int wid = tid >> 5, lid = tid & 31;
    const int m0 = blockIdx.x * 128;
    const int J0 = (wid >> 2) * 8;
    const int R = (wid & 3) * 32;

    if (tid < H) {
        sBias[tid] = bias[tid];
        sRo[tid] = g_rov[tid];
    }
    stage_tile<false>(A, nullptr, sAhi, sAlo, m0, M, tid);
    __syncthreads();

    float acc[2][8][4];
#pragma unroll
    for (int m = 0; m < 2; m++)
#pragma unroll
        for (int j = 0; j < 8; j++)
#pragma unroll
            for (int r = 0; r < 4; r++) acc[m][j][r] = 0.0f;

    mma_pass(smem_addr_u32(sAhi), smem_addr_u32(sAlo), Wf, J0, lid, R, acc);

    const int r0 = m0 + R;
    const int cb = (wid >> 2) * 64;
    const int g = lid >> 2, tg = lid & 3;
    const float roc = g_roc[0];
    float dots[4] = {0.f, 0.f, 0.f, 0.f};
#pragma unroll
    for (int m = 0; m < 2; m++)
#pragma unroll
        for (int rh = 0; rh < 2; rh++) {
            int row = r0 + m * 16 + rh * 8 + g;
            if (row < M) {
                float dv = 0.f;
#pragma unroll
                for (int j = 0; j < 8; j++) {
                    int c = cb + j * 8 + tg * 2;
                    float zx = fmaxf(acc[m][j][rh * 2 + 0] + sBias[c], 0.f);
                    float zy = fmaxf(acc[m][j][rh * 2 + 1] + sBias[c + 1], 0.f);
                    dv += zx * sRo[c] + zy * sRo[c + 1];
                }
                dots[m * 2 + rh] = dv;
            }
        }
#pragma unroll
    for (int s = 0; s < 4; s++) {
        float v = dots[s];
        v += __shfl_xor_sync(0xffffffff, v, 1);
        v += __shfl_xor_sync(0xffffffff, v, 2);
        int row = r0 + (s >> 1) * 16 + (s & 1) * 8 + g;
        if (tg == 0 && row < M) {
            if (cb == 0) v += roc;
            atomicAdd(gout + __ldg(batch + row), v);
        }
    }
}

// ---------------- launcher ------------------------------------------------------
extern "C" void kernel_launch(void* const* d_in, const int* in_sizes, int n_in,
                              void* d_out, int out_size) {
    const int*   x      = (const int*)d_in[0];
    const int*   ei     = (const int*)d_in[1];
    const int*   batch  = (const int*)d_in[2];
    const float* table  = (const float*)d_in[3];
    const float* bn_g   = (const float*)d_in[4];
    const float* bn_b   = (const float*)d_in[5];
    const float* bn_m   = (const float*)d_in[6];
    const float* bn_v   = (const float*)d_in[7];
    const float* lin_w  = (const float*)d_in[8];
    const float* lin_b  = (const float*)d_in[9];
    const float* eps    = (const float*)d_in[10];
    const float* mlp_w1 = (const float*)d_in[11];
    const float* mlp_b1 = (const float*)d_in[12];
    const float* mbn_g  = (const float*)d_in[13];
    const float* mbn_b  = (const float*)d_in[14];
    const float* mbn_m  = (const float*)d_in[15];
    const float* mbn_v  = (const float*)d_in[16];
    const float* mlp_w2 = (const float*)d_in[17];
    const float* mlp_b2 = (const float*)d_in[18];
    const float* ro_w   = (const float*)d_in[19];
    const float* ro_b   = (const float*)d_in[20];

    const int Nn = in_sizes[0];
    const int Ee = in_sizes[1] / 2;
    const int Gg = out_size;

    float *t, *agg, *bf;
    uint4* Wf;
    cudaGetSymbolAddress((void**)&t,   g_t);
    cudaGetSymbolAddress((void**)&agg, g_agg);
    cudaGetSymbolAddress((void**)&Wf,  g_Wfrag);
    cudaGetSymbolAddress((void**)&bf,  g_bf);

    cudaFuncSetAttribute(gemm_embed, cudaFuncAttributeMaxDynamicSharedMemorySize, SM_TOTAL_G);
    cudaFuncSetAttribute(gemm_dual,  cudaFuncAttributeMaxDynamicSharedMemorySize, SM_TOTAL_G);
    cudaFuncSetAttribute(gemm_ro,    cudaFuncAttributeMaxDynamicSharedMemorySize, SM_TOTAL_G);

    const int gemm_grid = (Nn + 127) / 128;
    const int edge_grid = (Ee + 255) / 256;
    const int node_grid = (Nn + 1023) / 1024;
    const int warp_grid = ((Nn * 32) + 255) / 256;

    const size_t SLOT = (size_t)16 * 8 * 32;

    // #1..#3: fold pipeline (fp32 scale -> combined matmul -> fragment pack)
    fold_scale_kernel<<<6, H>>>(bn_g, bn_b, bn_m, bn_v, lin_w, lin_b,
                                mbn_g, mbn_b, mbn_m, mbn_v, mlp_w1, mlp_b1);
    fold_mm_kernel<<<9, 256>>>(mlp_w2, mlp_b2, ro_w, ro_b);
    pack_kernel<<<6, H>>>();
    // #4: G1 (profiled launch)
    gemm_embed<<<gemm_grid, 256, SM_TOTAL_G>>>(table, x, Wf, bf, t, Nn);
    // output zero + CSR build
    zero_out_kernel<<<(Gg + 255) / 256, 256>>>((float*)d_out, Gg);
    zero_csr_kernel<<<(Nn + 255) / 256, 256>>>(Nn);
    hist_kernel<<<edge_grid, 256>>>(ei, Ee);
    scan_block_kernel<<<node_grid, 1024>>>(Nn);
    scan_bsum_kernel<<<1, 32>>>(node_grid);
    scan_final_kernel<<<node_grid, 1024>>>(Nn);
    fill_csr_kernel<<<edge_grid, 256>>>(ei, Ee);

    // layers 0,1: gather + dual (z-GEMM then combined W2*SL GEMM -> next t)
    for (int l = 0; l < 2; l++) {
        gather_kernel<<<warp_grid, 256>>>(t, eps, l, agg, Nn);
        gemm_dual<<<gemm_grid, 256, SM_TOTAL_G>>>(
            agg,
            Wf + (1 + 2 * l) * SLOT, bf + (1 + 2 * l) * H,
            Wf + (2 + 2 * l) * SLOT, bf + (2 + 2 * l) * H,
            t, Nn);
    }
    // layer 2: gather + z-GEMM with folded readout (h never materialized)
    gather_kernel<<<warp_grid, 256>>>(t, eps, 2, agg, Nn);
    gemm_ro<<<gemm_grid, 256, SM_TOTAL_G>>>(
        agg, Wf + 5 * SLOT, bf + 5 * H, batch, (float*)d_out, Nn);
}